// round 14
// baseline (speedup 1.0000x reference)
#include <cuda_runtime.h>
#include <cuda_bf16.h>
#include <math.h>
#include <cstdint>

#define BB 512
#define CC 12
#define WW 4
#define FF 512
#define NN 2048      // B*W
#define G3 1536      // 3*F
#define MROWS 24576  // C*N rows

// ---------------- scratch (device globals; no allocation allowed) ----------
__device__ float g_xW [MROWS * G3];    // [C][N][3F] input gate preacts
__device__ float g_hgp[3 * NN * G3];   // split-K partials for recurrent GEMM
__device__ float g_hs [CC * NN * FF];  // [C][N][F]  h after each step
__device__ float g_y1 [BB * CC * FF];
__device__ float g_y2 [BB * CC];
__device__ float g_am [CC * CC];
__device__ float g_cheb[4 * CC * CC];
__device__ float g_h1 [MROWS * FF];    // [C][N][F]
__device__ float g_h2 [MROWS * FF];
__device__ float g_supp[MROWS * FF];
__device__ float g_pool[BB * CC * FF]; // [B, C*F]
__device__ float g_fcpart[8 * 512 * 512];
__device__ float g_z1 [BB * 512];
__device__ float g_z2 [BB * 512];
__device__ int   g_tick[64];           // gate-tile tickets (self-resetting)
// bf16 hi/lo planes for tensor-core GEMMs
__device__ __nv_bfloat16 g_axh [MROWS * FF], g_axl [MROWS * FF];   // gathered x
__device__ __nv_bfloat16 g_hbh [CC * NN * FF], g_hbl [CC * NN * FF]; // GRU h
__device__ __nv_bfloat16 g_h1bh[MROWS * FF], g_h1bl[MROWS * FF];   // GCN h1
__device__ __nv_bfloat16 g_wihh[G3 * FF], g_wihl[G3 * FF];
__device__ __nv_bfloat16 g_whhh[G3 * FF], g_whhl[G3 * FF];
__device__ __nv_bfloat16 g_g0h [FF * FF], g_g0l [FF * FF];         // gcnw0^T [N,K]
__device__ __nv_bfloat16 g_g1h [FF * FF], g_g1l [FF * FF];         // gcnw1^T [N,K]

__device__ __forceinline__ void mma16816(float* d, const uint32_t* a, const uint32_t* b) {
    asm volatile(
        "mma.sync.aligned.m16n8k16.row.col.f32.bf16.bf16.f32 "
        "{%0,%1,%2,%3}, {%4,%5,%6,%7}, {%8,%9}, {%0,%1,%2,%3};\n"
        : "+f"(d[0]), "+f"(d[1]), "+f"(d[2]), "+f"(d[3])
        : "r"(a[0]), "r"(a[1]), "r"(a[2]), "r"(a[3]), "r"(b[0]), "r"(b[1]));
}
__device__ __forceinline__ void ldm_x4(uint32_t* r, uint32_t addr) {
    asm volatile("ldmatrix.sync.aligned.m8n8.x4.shared.b16 {%0,%1,%2,%3}, [%4];"
        : "=r"(r[0]), "=r"(r[1]), "=r"(r[2]), "=r"(r[3]) : "r"(addr));
}
__device__ __forceinline__ void split_bf(float v, __nv_bfloat16& h, __nv_bfloat16& l) {
    h = __float2bfloat16(v);
    l = __float2bfloat16(v - __bfloat162float(h));
}

// ---- shared gate math: one float4 column-chunk of one row ------------------
__device__ __forceinline__ void gate_store4(size_t o, const float* h) {
    *(float4*)&g_hs[o] = make_float4(h[0], h[1], h[2], h[3]);
    __align__(8) __nv_bfloat16 hh[4], hl[4];
    #pragma unroll
    for (int i = 0; i < 4; i++) split_bf(h[i], hh[i], hl[i]);
    *(uint2*)&g_hbh[o] = *(uint2*)hh;
    *(uint2*)&g_hbl[o] = *(uint2*)hl;
}

__device__ __forceinline__ void gate_elem4(int t, int n, int f, const float* __restrict__ bhh) {
    const size_t base = (size_t)n * G3;
    const float* p0 = g_hgp + base;
    const float* p1 = g_hgp + (size_t)NN * G3 + base;
    const float* p2 = g_hgp + (size_t)2 * NN * G3 + base;
    float hr[4], hz[4], hn[4];
    #pragma unroll
    for (int g = 0; g < 3; g++) {
        float* dst = (g == 0) ? hr : (g == 1) ? hz : hn;
        const int off = g * 512 + f;
        float4 a = *(const float4*)&p0[off];
        float4 b = *(const float4*)&p1[off];
        float4 c = *(const float4*)&p2[off];
        float4 d = *(const float4*)&bhh[off];
        dst[0] = a.x + b.x + c.x + d.x;
        dst[1] = a.y + b.y + c.y + d.y;
        dst[2] = a.z + b.z + c.z + d.z;
        dst[3] = a.w + b.w + c.w + d.w;
    }
    const float* xw = g_xW + ((size_t)t * NN + n) * G3;
    float4 xr = *(const float4*)&xw[f];
    float4 xz = *(const float4*)&xw[512 + f];
    float4 xn = *(const float4*)&xw[1024 + f];
    float4 hp = *(const float4*)&g_hs[((size_t)(t - 1) * NN + n) * FF + f];
    float h[4];
    #pragma unroll
    for (int i = 0; i < 4; i++) {
        float r = 1.f / (1.f + expf(-(((const float*)&xr)[i] + hr[i])));
        float z = 1.f / (1.f + expf(-(((const float*)&xz)[i] + hz[i])));
        float nv = tanhf(((const float*)&xn)[i] + r * hn[i]);
        h[i] = (1.f - z) * nv + z * ((const float*)&hp)[i];
    }
    gate_store4(((size_t)t * NN + n) * FF + f, h);
}

// ================= HMMA bf16 hi/lo split GEMM (fused 3-combo) ===============
// D[M,N] fp32 = (Ah+Al)*(Bh+Bl)^T - Al*Bl^T  (lo*lo dropped)
// 3-stage single-barrier cp.async pipeline; dense 64B rows with chunk-XOR swizzle.
// kSplit>1: grid.z splits K chunks; partial z -> C + z*M*N.
// gateT>0: recurrent mode — last of the 9 blocks feeding a 128x128 gate tile
// runs the GRU gate math in-kernel (threadfence-reduction ticket).
#define MATB 8192                    // bytes per matrix tile (128 rows x 64B)
#define STAGE4 (4 * MATB)            // Ah|Al|Bh|Bl  = 32768 bytes
#define GEMM_SMEM (3 * STAGE4)       // 98304 bytes (3 stages)

__global__ void __launch_bounds__(256, 2)
gemmMMA(const __nv_bfloat16* __restrict__ Ah, const __nv_bfloat16* __restrict__ Al,
        const __nv_bfloat16* __restrict__ Bh, const __nv_bfloat16* __restrict__ Bl,
        const float* __restrict__ bias, float* __restrict__ C, int M, int N, int K,
        int kSplit, int gateT, const float* __restrict__ bhh)
{
    extern __shared__ __align__(16) char dyn[];
    const uint32_t Su32 = (uint32_t)__cvta_generic_to_shared(dyn);

    const int tid = threadIdx.x, wid = tid >> 5, lane = tid & 31;
    const int wm = wid & 3, wn = wid >> 2;
    const int bm = blockIdx.y * 128, bn = blockIdx.x * 128;
    const int r = lane >> 2, cq = lane & 3;

    const __nv_bfloat16* mat[4] = {
        Ah + (size_t)bm * K, Al + (size_t)bm * K,
        Bh + (size_t)bn * K, Bl + (size_t)bn * K };
    const int KCH = K >> 5;
    const int cps = KCH / kSplit, rem = KCH % kSplit;
    const int z = blockIdx.z;
    const int c0 = z * cps + (z < rem ? z : rem);
    const int c1 = c0 + cps + (z < rem ? 1 : 0);
    C += (size_t)z * M * N;

    float acc[2][8][4];
    #pragma unroll
    for (int mi = 0; mi < 2; mi++)
        #pragma unroll
        for (int ni = 0; ni < 8; ni++)
            #pragma unroll
            for (int q = 0; q < 4; q++) acc[mi][ni][q] = 0.f;

    const int prow = tid >> 2, pch = tid & 3;
    auto prefetch = [&](int c) {
        const int k0 = c << 5;
        const uint32_t st = (uint32_t)((c % 3) * STAGE4);
        #pragma unroll
        for (int m = 0; m < 4; m++) {
            #pragma unroll
            for (int i = 0; i < 2; i++) {
                const int row = prow + i * 64;
                const uint32_t dst = Su32 + st + (uint32_t)m * MATB +
                                     (uint32_t)row * 64 +
                                     ((uint32_t)(pch ^ (row & 3)) << 4);
                const __nv_bfloat16* src = mat[m] + (size_t)row * K + k0 + pch * 8;
                asm volatile("cp.async.cg.shared.global [%0], [%1], 16;"
                             :: "r"(dst), "l"(src) : "memory");
            }
        }
        asm volatile("cp.async.commit_group;" ::: "memory");
    };

    const int a_row = lane & 15;
    const int a_sel = lane >> 4;
    const int b_row = ((lane >> 4) << 3) + (lane & 7);
    const int b_sel = (lane >> 3) & 1;
    const int lxor = lane & 3;

    prefetch(c0);
    if (c0 + 1 < c1) prefetch(c0 + 1);
    for (int c = c0; c < c1; c++) {
        if (c + 1 < c1) asm volatile("cp.async.wait_group 1;" ::: "memory");
        else            asm volatile("cp.async.wait_group 0;" ::: "memory");
        __syncthreads();
        if (c + 2 < c1) prefetch(c + 2);

        const uint32_t S = Su32 + (uint32_t)((c % 3) * STAGE4);
        const uint32_t SAh = S, SAl = S + MATB, SBh = S + 2 * MATB, SBl = S + 3 * MATB;
        #pragma unroll
        for (int ks = 0; ks < 2; ks++) {
            const uint32_t axor = (uint32_t)((ks * 2 + a_sel) ^ lxor) << 4;
            const uint32_t bxor = (uint32_t)((ks * 2 + b_sel) ^ lxor) << 4;
            uint32_t ah[2][4], al[2][4], bf[8][2];
            #pragma unroll
            for (int mi = 0; mi < 2; mi++) {
                const uint32_t ra = (uint32_t)(wm * 32 + mi * 16 + a_row) * 64 + axor;
                ldm_x4(ah[mi], SAh + ra);
            }
            #pragma unroll
            for (int nj = 0; nj < 4; nj++) {
                const uint32_t rb = (uint32_t)(wn * 64 + nj * 16 + b_row) * 64 + bxor;
                uint32_t q[4];
                ldm_x4(q, SBh + rb);
                bf[2 * nj][0] = q[0]; bf[2 * nj][1] = q[1];
                bf[2 * nj + 1][0] = q[2]; bf[2 * nj + 1][1] = q[3];
            }
            #pragma unroll
            for (int mi = 0; mi < 2; mi++)
                #pragma unroll
                for (int ni = 0; ni < 8; ni++)
                    mma16816(acc[mi][ni], ah[mi], bf[ni]);
            #pragma unroll
            for (int mi = 0; mi < 2; mi++) {
                const uint32_t ra = (uint32_t)(wm * 32 + mi * 16 + a_row) * 64 + axor;
                ldm_x4(al[mi], SAl + ra);
            }
            #pragma unroll
            for (int mi = 0; mi < 2; mi++)
                #pragma unroll
                for (int ni = 0; ni < 8; ni++)
                    mma16816(acc[mi][ni], al[mi], bf[ni]);
            #pragma unroll
            for (int nj = 0; nj < 4; nj++) {
                const uint32_t rb = (uint32_t)(wn * 64 + nj * 16 + b_row) * 64 + bxor;
                uint32_t q[4];
                ldm_x4(q, SBl + rb);
                bf[2 * nj][0] = q[0]; bf[2 * nj][1] = q[1];
                bf[2 * nj + 1][0] = q[2]; bf[2 * nj + 1][1] = q[3];
            }
            #pragma unroll
            for (int mi = 0; mi < 2; mi++)
                #pragma unroll
                for (int ni = 0; ni < 8; ni++)
                    mma16816(acc[mi][ni], ah[mi], bf[ni]);
        }
    }

    #pragma unroll
    for (int mi = 0; mi < 2; mi++) {
        const int row0 = bm + wm * 32 + mi * 16 + r;
        #pragma unroll
        for (int ni = 0; ni < 8; ni++) {
            const int col = bn + wn * 64 + ni * 8 + cq * 2;
            float b0 = 0.f, b1 = 0.f;
            if (bias) { b0 = bias[col]; b1 = bias[col + 1]; }
            float2 v0 = make_float2(acc[mi][ni][0] + b0, acc[mi][ni][1] + b1);
            float2 v1 = make_float2(acc[mi][ni][2] + b0, acc[mi][ni][3] + b1);
            *(float2*)&C[(size_t)row0 * N + col] = v0;
            *(float2*)&C[(size_t)(row0 + 8) * N + col] = v1;
        }
    }

    // ---- recurrent mode: last-of-9 block runs the gate tile ----------------
    if (gateT > 0) {
        const int jf = blockIdx.x & 3;                 // gate f-chunk
        const int gid = blockIdx.y * 4 + jf;
        __shared__ int sflag;
        __threadfence();                                // publish C partial
        __syncthreads();
        if (tid == 0) {
            int old = atomicAdd(&g_tick[gid], 1);
            sflag = (old == 8);
            if (old == 8) g_tick[gid] = 0;              // self-reset for next step
        }
        __syncthreads();
        if (!sflag) return;
        __threadfence();                                // acquire others' partials
        const int f0 = jf * 128;
        #pragma unroll 4
        for (int j = tid; j < 128 * 32; j += 256) {     // 128 rows x 32 float4
            const int n = bm + (j >> 5);
            const int f = f0 + (j & 31) * 4;
            gate_elem4(gateT, n, f, bhh);
        }
    }
}

// ================= fp32 128x128 GEMM (head only) ============================
template<bool TRANSB, int AMAP, int EPI>
__global__ void __launch_bounds__(256, 2)
gemm128(const float* __restrict__ A, const float* __restrict__ B,
        const float* __restrict__ bias, float* __restrict__ C,
        int M, int N, int K, int kChunk)
{
    __shared__ float As[16][132];
    __shared__ float Bs[16][132];
    const int tid = threadIdx.x;
    const int tx = tid & 15, ty = tid >> 4;
    const int bm = blockIdx.y * 128, bn = blockIdx.x * 128;
    int ks = 0, ke = K;
    if (kChunk > 0) {
        ks = blockIdx.z * kChunk; ke = ks + kChunk;
        C += (size_t)blockIdx.z * M * N;
    }
    const int lr = tid >> 2;
    const int lc = (tid & 3) * 4;
    const int bR = tid >> 5;
    const int bC = (tid & 31) * 4;
    size_t aRow0 = (size_t)(bm + lr), aRow1 = (size_t)(bm + lr + 64);

    float4 pa0, pa1, pb0, pb1;
    auto loadg = [&](int k0) {
        pa0 = *(const float4*)&A[aRow0 * K + k0 + lc];
        pa1 = *(const float4*)&A[aRow1 * K + k0 + lc];
        if (TRANSB) {
            pb0 = *(const float4*)&B[(size_t)(bn + lr) * K + k0 + lc];
            pb1 = *(const float4*)&B[(size_t)(bn + lr + 64) * K + k0 + lc];
        } else {
            pb0 = *(const float4*)&B[(size_t)(k0 + bR) * N + bn + bC];
            pb1 = *(const float4*)&B[(size_t)(k0 + bR + 8) * N + bn + bC];
        }
    };
    unsigned long long acc[8][4];
    #pragma unroll
    for (int i = 0; i < 8; i++)
        #pragma unroll
        for (int j = 0; j < 4; j++) acc[i][j] = 0ULL;
    loadg(ks);
    for (int k0 = ks; k0 < ke; k0 += 16) {
        As[lc + 0][lr] = pa0.x; As[lc + 1][lr] = pa0.y;
        As[lc + 2][lr] = pa0.z; As[lc + 3][lr] = pa0.w;
        As[lc + 0][lr + 64] = pa1.x; As[lc + 1][lr + 64] = pa1.y;
        As[lc + 2][lr + 64] = pa1.z; As[lc + 3][lr + 64] = pa1.w;
        if (TRANSB) {
            Bs[lc + 0][lr] = pb0.x; Bs[lc + 1][lr] = pb0.y;
            Bs[lc + 2][lr] = pb0.z; Bs[lc + 3][lr] = pb0.w;
            Bs[lc + 0][lr + 64] = pb1.x; Bs[lc + 1][lr + 64] = pb1.y;
            Bs[lc + 2][lr + 64] = pb1.z; Bs[lc + 3][lr + 64] = pb1.w;
        } else {
            *(float4*)&Bs[bR][bC]     = pb0;
            *(float4*)&Bs[bR + 8][bC] = pb1;
        }
        __syncthreads();
        if (k0 + 16 < ke) loadg(k0 + 16);
        #pragma unroll
        for (int k = 0; k < 16; k++) {
            float4 a0 = *(const float4*)&As[k][ty * 4];
            float4 a1 = *(const float4*)&As[k][64 + ty * 4];
            ulonglong2 b0 = *(const ulonglong2*)&Bs[k][tx * 4];
            ulonglong2 b1 = *(const ulonglong2*)&Bs[k][64 + tx * 4];
            float ar[8] = {a0.x, a0.y, a0.z, a0.w, a1.x, a1.y, a1.z, a1.w};
            unsigned long long bp[4] = {b0.x, b0.y, b1.x, b1.y};
            #pragma unroll
            for (int i = 0; i < 8; i++) {
                unsigned long long ad;
                asm("mov.b64 %0, {%1, %1};" : "=l"(ad) : "f"(ar[i]));
                #pragma unroll
                for (int j = 0; j < 4; j++)
                    asm("fma.rn.f32x2 %0, %1, %2, %0;"
                        : "+l"(acc[i][j]) : "l"(ad), "l"(bp[j]));
            }
        }
        __syncthreads();
    }
    #pragma unroll
    for (int i = 0; i < 8; i++) {
        int gm = bm + ((i < 4) ? (ty * 4 + i) : (60 + ty * 4 + i));
        float v[8];
        #pragma unroll
        for (int j = 0; j < 4; j++)
            asm("mov.b64 {%0, %1}, %2;"
                : "=f"(v[2 * j]), "=f"(v[2 * j + 1]) : "l"(acc[i][j]));
        #pragma unroll
        for (int h = 0; h < 2; h++) {
            int gn = bn + (h ? 64 + tx * 4 : tx * 4);
            float t0 = v[h * 4], t1 = v[h * 4 + 1], t2 = v[h * 4 + 2], t3 = v[h * 4 + 3];
            if (EPI >= 1) {
                t0 += bias[gn + 0]; t1 += bias[gn + 1];
                t2 += bias[gn + 2]; t3 += bias[gn + 3];
            }
            float4 o; o.x = t0; o.y = t1; o.z = t2; o.w = t3;
            *(float4*)&C[(size_t)gm * N + gn] = o;
        }
    }
}

// ================= conversions =============================================
__global__ void k_cvt(const float* __restrict__ src, __nv_bfloat16* __restrict__ hi,
                      __nv_bfloat16* __restrict__ lo, int n) {
    int i = blockIdx.x * blockDim.x + threadIdx.x;
    if (i >= n) return;
    split_bf(src[i], hi[i], lo[i]);
}

// gcn weight [K,N] -> planes [N,K]
__global__ void k_cvtT(const float* __restrict__ W, __nv_bfloat16* __restrict__ hi,
                       __nv_bfloat16* __restrict__ lo) {
    int i = blockIdx.x * blockDim.x + threadIdx.x;
    if (i >= FF * FF) return;
    int n = i >> 9, k = i & 511;
    split_bf(W[k * FF + n], hi[i], lo[i]);
}

// gather x -> A planes [C][N][F]
__global__ void k_cvt_x(const float* __restrict__ x) {
    int idx = blockIdx.x * blockDim.x + threadIdx.x;
    if (idx >= MROWS * FF) return;
    int f = idx & 511;
    int r = idx >> 9;
    int t = r / NN, n = r - t * NN;
    int b = n >> 2, w = n & 3;
    float v = x[(((size_t)b * CC + t) * WW + w) * FF + f];
    split_bf(v, g_axh[idx], g_axl[idx]);
}

// ================= GRU gate t=0 =============================================
__global__ void k_gru_gate0(const float* __restrict__ bhh) {
    int idx = blockIdx.x * blockDim.x + threadIdx.x;
    if (idx >= NN * FF / 4) return;
    int n = idx >> 7, f = (idx & 127) * 4;
    const float* xw = g_xW + (size_t)n * G3;
    float4 xr = *(const float4*)&xw[f];
    float4 xz = *(const float4*)&xw[512 + f];
    float4 xn = *(const float4*)&xw[1024 + f];
    float4 br = *(const float4*)&bhh[f];
    float4 bz = *(const float4*)&bhh[512 + f];
    float4 bn = *(const float4*)&bhh[1024 + f];
    float h[4];
    #pragma unroll
    for (int i = 0; i < 4; i++) {
        float xri = ((const float*)&xr)[i] + ((const float*)&br)[i];
        float xzi = ((const float*)&xz)[i] + ((const float*)&bz)[i];
        float xni = ((const float*)&xn)[i];
        float bni = ((const float*)&bn)[i];
        float r = 1.f / (1.f + expf(-xri));
        float z = 1.f / (1.f + expf(-xzi));
        float nv = tanhf(xni + r * bni);
        h[i] = (1.f - z) * nv;
    }
    gate_store4((size_t)n * FF + f, h);
}

// ================= graph learning ==========================================
__global__ void k_y1(const float* __restrict__ w, const float* __restrict__ b0) {
    int idx = blockIdx.x * blockDim.x + threadIdx.x;
    if (idx >= BB * CC * FF) return;
    int f = idx & 511;
    int r = idx >> 9;
    int c = r % 12, b = r / 12;
    float s = b0[0];
    #pragma unroll
    for (int wi = 0; wi < 4; wi++)
        s += g_hs[((size_t)c * NN + (b * 4 + wi)) * FF + f] * w[wi];
    g_y1[idx] = fmaxf(s, 0.f);
}

__global__ void k_y2(const float* __restrict__ w, const float* __restrict__ b1) {
    int r = blockIdx.x;
    float s = 0.f;
    for (int f = threadIdx.x; f < 512; f += 128)
        s += g_y1[(size_t)r * 512 + f] * w[f];
    __shared__ float red[4];
    for (int o = 16; o; o >>= 1) s += __shfl_down_sync(0xffffffffu, s, o);
    if ((threadIdx.x & 31) == 0) red[threadIdx.x >> 5] = s;
    __syncthreads();
    if (threadIdx.x == 0)
        g_y2[r] = fmaxf(red[0] + red[1] + red[2] + red[3] + b1[0], 0.f);
}

__global__ void k_y3mean(const float* __restrict__ w2, const float* __restrict__ b2) {
    int k = blockIdx.x;
    float wl[12];
    #pragma unroll
    for (int c = 0; c < 12; c++) wl[c] = w2[k * 12 + c];
    float bk = b2[k];
    float s = 0.f;
    for (int b = threadIdx.x; b < 512; b += 256) {
        float v = bk;
        #pragma unroll
        for (int c = 0; c < 12; c++) v += g_y2[b * 12 + c] * wl[c];
        s += fmaxf(v, 0.f);
    }
    __shared__ float red[8];
    for (int o = 16; o; o >>= 1) s += __shfl_down_sync(0xffffffffu, s, o);
    if ((threadIdx.x & 31) == 0) red[threadIdx.x >> 5] = s;
    __syncthreads();
    if (threadIdx.x == 0) {
        float t = 0.f;
        #pragma unroll
        for (int i = 0; i < 8; i++) t += red[i];
        g_am[k] = t * (1.f / 512.f);
    }
}

__global__ void k_cheb() {
    __shared__ float adj[144], lap[144], L2s[144], deg[12], dh[12];
    int t = threadIdx.x;
    if (t < 144) adj[t] = fmaxf(g_am[t], 0.f);
    __syncthreads();
    if (t < 12) {
        float s = 0.f;
        #pragma unroll
        for (int j = 0; j < 12; j++) s += adj[t * 12 + j];
        deg[t] = s;
        dh[t] = 1.f / (sqrtf(s) + 1e-7f);
    }
    __syncthreads();
    if (t < 144) {
        int i = t / 12, j = t % 12;
        float as = 0.5f * (adj[i * 12 + j] + adj[j * 12 + i]);
        lap[t] = dh[i] * (((i == j) ? deg[i] : 0.f) - as) * dh[j];
    }
    __syncthreads();
    if (t < 144) {
        int i = t / 12, j = t % 12;
        float s = 0.f;
        #pragma unroll
        for (int k = 0; k < 12; k++) s += lap[i * 12 + k] * lap[k * 12 + j];
        L2s[t] = 2.f * s;
    }
    __syncthreads();
    if (t < 144) {
        int i = t / 12, j = t % 12;
        float s = 0.f;
        #pragma unroll
        for (int k = 0; k < 12; k++) s += lap[i * 12 + k] * L2s[k * 12 + j];
        g_cheb[t]       = 0.f;
        g_cheb[144 + t] = lap[t];
        g_cheb[288 + t] = L2s[t];
        g_cheb[432 + t] = 2.f * s - lap[t];
    }
}

// ============ GCN: cheb mix + bias + relu + residual ([C][N][F]) ============
__global__ void k_gcnpost(const float* __restrict__ Hres, const float* __restrict__ gcnb,
                          float* __restrict__ Hout,
                          __nv_bfloat16* __restrict__ Ohi, __nv_bfloat16* __restrict__ Olo) {
    int blk = blockIdx.x;
    int n = blk >> 2;
    int chunk = blk & 3;
    int w = n & 3;
    int f = chunk * 128 + threadIdx.x;
    __shared__ float s[12][129];
    __shared__ float ch[144];
    for (int i = threadIdx.x; i < 144; i += 128) ch[i] = g_cheb[w * 144 + i];
    #pragma unroll
    for (int j = 0; j < 12; j++)
        s[j][threadIdx.x] = g_supp[((size_t)j * NN + n) * 512 + f];
    __syncthreads();
    float bias = gcnb[f];
    #pragma unroll
    for (int i = 0; i < 12; i++) {
        float acc = bias;
        #pragma unroll
        for (int j = 0; j < 12; j++)
            acc = fmaf(ch[i * 12 + j], s[j][threadIdx.x], acc);
        size_t o = ((size_t)i * NN + n) * 512 + f;
        float hv = fmaxf(acc, 0.f) + Hres[o];
        Hout[o] = hv;
        if (Ohi) split_bf(hv, Ohi[o], Olo[o]);
    }
}

// ================= pool over W + flatten ====================================
__global__ void k_pool() {
    int idx = blockIdx.x * blockDim.x + threadIdx.x;
    if (idx >= BB * CC * FF) return;
    int f = idx & 511;
    int r = idx >> 9;
    int c = r % 12, b = r / 12;
    float s = 0.f;
    #pragma unroll
    for (int w = 0; w < 4; w++) {
        size_t o = ((size_t)c * NN + (b * 4 + w)) * 512 + f;
        s += g_hs[o] + g_h2[o];
    }
    g_pool[idx] = s;
}

// ================= split-K reduce + leaky + BN ==============================
__global__ void k_fcreduce(int S, const float* __restrict__ bias,
                           const float* __restrict__ bng, const float* __restrict__ bnb,
                           const float* __restrict__ bnm, const float* __restrict__ bnv,
                           float* __restrict__ out) {
    int idx = blockIdx.x * blockDim.x + threadIdx.x;
    if (idx >= 512 * 512) return;
    float s = 0.f;
    for (int p = 0; p < S; p++) s += g_fcpart[(size_t)p * 512 * 512 + idx];
    int c = idx & 511;
    s += bias[c];
    s = s > 0.f ? s : 0.01f * s;
    s = (s - bnm[c]) * rsqrtf(bnv[c] + 1e-5f) * bng[c] + bnb[c];
    out[idx] = s;
}

// ================= fc3 (N=4) ================================================
__global__ void k_fc3(const float* __restrict__ w, const float* __restrict__ b,
                      float* __restrict__ out) {
    int bb = blockIdx.x;
    float s0 = 0.f, s1 = 0.f, s2 = 0.f, s3 = 0.f;
    for (int j = threadIdx.x; j < 512; j += 128) {
        float v = g_z2[bb * 512 + j];
        const float* wr = w + j * 4;
        s0 += v * wr[0]; s1 += v * wr[1]; s2 += v * wr[2]; s3 += v * wr[3];
    }
    __shared__ float red[4][4];
    for (int o = 16; o; o >>= 1) {
        s0 += __shfl_down_sync(0xffffffffu, s0, o);
        s1 += __shfl_down_sync(0xffffffffu, s1, o);
        s2 += __shfl_down_sync(0xffffffffu, s2, o);
        s3 += __shfl_down_sync(0xffffffffu, s3, o);
    }
    int wid = threadIdx.x >> 5;
    if ((threadIdx.x & 31) == 0) {
        red[wid][0] = s0; red[wid][1] = s1; red[wid][2] = s2; red[wid][3] = s3;
    }
    __syncthreads();
    if (threadIdx.x < 4) {
        float t = red[0][threadIdx.x] + red[1][threadIdx.x] +
                  red[2][threadIdx.x] + red[3][threadIdx.x];
        out[bb * 4 + threadIdx.x] = t + b[threadIdx.x];
    }
}

// ================= launch ===================================================
extern "C" void kernel_launch(void* const* d_in, const int* in_sizes, int n_in,
                              void* d_out, int out_size) {
    const float* x    = (const float*)d_in[0];
    const float* wih  = (const float*)d_in[1];
    const float* whh  = (const float*)d_in[2];
    const float* bih  = (const float*)d_in[3];
    const float* bhh  = (const float*)d_in[4];
    const float* c0w  = (const float*)d_in[5];
    const float* c0b  = (const float*)d_in[6];
    const float* c1w  = (const float*)d_in[7];
    const float* c1b  = (const float*)d_in[8];
    const float* c2w  = (const float*)d_in[9];
    const float* c2b  = (const float*)d_in[10];
    const float* gcnw = (const float*)d_in[11];
    const float* gcnb = (const float*)d_in[12];
    const float* fc1w = (const float*)d_in[13];
    const float* fc1b = (const float*)d_in[14];
    const float* bn1g = (const float*)d_in[15];
    const float* bn1b = (const float*)d_in[16];
    const float* bn1m = (const float*)d_in[17];
    const float* bn1v = (const float*)d_in[18];
    const float* fc2w = (const float*)d_in[19];
    const float* fc2b = (const float*)d_in[20];
    const float* bn2g = (const float*)d_in[21];
    const float* bn2b = (const float*)d_in[22];
    const float* bn2m = (const float*)d_in[23];
    const float* bn2v = (const float*)d_in[24];
    const float* fc3w = (const float*)d_in[25];
    const float* fc3b = (const float*)d_in[26];
    float* out = (float*)d_out;

    cudaFuncSetAttribute(gemmMMA, cudaFuncAttributeMaxDynamicSharedMemorySize, GEMM_SMEM);

    float *p_xW, *p_hgp, *p_hs, *p_h1, *p_h2, *p_supp, *p_pool, *p_part, *p_z1, *p_z2;
    cudaGetSymbolAddress((void**)&p_xW,  g_xW);
    cudaGetSymbolAddress((void**)&p_hgp, g_hgp);
    cudaGetSymbolAddress((void**)&p_hs,  g_hs);
    cudaGetSymbolAddress((void**)&p_h1,  g_h1);
    cudaGetSymbolAddress((void**)&p_h2,  g_h2);
    cudaGetSymbolAddress((void**)&p_supp, g_supp);
    cudaGetSymbolAddress((void**)&p_pool, g_pool);
    cudaGetSymbolAddress((void**)&p_part, g_fcpart);
    cudaGetSymbolAddress((void**)&p_z1,  g_z1);
    cudaGetSymbolAddress((void**)&p_z2,  g_z2);
    __nv_bfloat16 *p_axh, *p_axl, *p_hbh, *p_hbl, *p_h1bh, *p_h1bl;
    __nv_bfloat16 *p_wihh, *p_wihl, *p_whhh, *p_whhl, *p_g0h, *p_g0l, *p_g1h, *p_g1l;
    cudaGetSymbolAddress((void**)&p_axh,  g_axh);
    cudaGetSymbolAddress((void**)&p_axl,  g_axl);
    cudaGetSymbolAddress((void**)&p_hbh,  g_hbh);
    cudaGetSymbolAddress((void**)&p_hbl,  g_hbl);
    cudaGetSymbolAddress((void**)&p_h1bh, g_h1bh);
    cudaGetSymbolAddress((void**)&p_h1bl, g_h1bl);
    cudaGetSymbolAddress((void**)&p_wihh, g_wihh);
    cudaGetSymbolAddress((void**)&p_wihl, g_wihl);
    cudaGetSymbolAddress((void**)&p_whhh, g_whhh);
    cudaGetSymbolAddress((void**)&p_whhl, g_whhl);
    cudaGetSymbolAddress((void**)&p_g0h,  g_g0h);
    cudaGetSymbolAddress((void**)&p_g0l,  g_g0l);
    cudaGetSymbolAddress((void**)&p_g1h,  g_g1h);
    cudaGetSymbolAddress((void**)&p_g1l,  g_g1l);

    // 0) input-side conversions
    k_cvt_x<<<(MROWS * FF + 255) / 256, 256>>>(x);
    k_cvt<<<(G3 * FF + 255) / 256, 256>>>(wih, p_wihh, p_wihl, G3 * FF);
    k_cvt<<<(G3 * FF + 255) / 256, 256>>>(whh, p_whhh, p_whhl, G3 * FF);

    // 1) input-gate preacts: [24576,1536] = x * wih^T + bih  (HMMA)
    gemmMMA<<<dim3(G3 / 128, MROWS / 128), 256, GEMM_SMEM>>>(
        p_axh, p_axl, p_wihh, p_wihl, bih, p_xW, MROWS, G3, FF, 1, 0, nullptr);

    // 2) 12 recurrent steps: split-K=3 GEMM with in-kernel gate (ticket)
    k_gru_gate0<<<(NN * FF / 4 + 255) / 256, 256>>>(bhh);
    for (int t = 1; t < CC; t++)
        gemmMMA<<<dim3(G3 / 128, NN / 128, 3), 256, GEMM_SMEM>>>(
            p_hbh + (size_t)(t - 1) * NN * FF, p_hbl + (size_t)(t - 1) * NN * FF,
            p_whhh, p_whhl, nullptr, p_hgp, NN, G3, FF, 3, t, bhh);

    // 3) graph learning -> chebyshev basis (+ GCN weight conversion)
    k_y1<<<(BB * CC * FF + 255) / 256, 256>>>(c0w, c0b);
    k_y2<<<BB * CC, 128>>>(c1w, c1b);
    k_y3mean<<<CC * CC, 256>>>(c2w, c2b);
    k_cheb<<<1, 160>>>();
    k_cvtT<<<(FF * FF + 255) / 256, 256>>>(gcnw, p_g0h, p_g0l);
    k_cvtT<<<(FF * FF + 255) / 256, 256>>>(gcnw + FF * FF, p_g1h, p_g1l);

    // 4) GCN layer 0
    gemmMMA<<<dim3(FF / 128, MROWS / 128), 256, GEMM_SMEM>>>(
        p_hbh, p_hbl, p_g0h, p_g0l, nullptr, p_supp, MROWS, FF, FF, 1, 0, nullptr);
    k_gcnpost<<<NN * 4, 128>>>(p_hs, gcnb, p_h1, p_h1bh, p_h1bl);

    // 5) GCN layer 1
    gemmMMA<<<dim3(FF / 128, MROWS / 128), 256, GEMM_SMEM>>>(
        p_h1bh, p_h1bl, p_g1h, p_g1l, nullptr, p_supp, MROWS, FF, FF, 1, 0, nullptr);
    k_gcnpost<<<NN * 4, 128>>>(p_h1, gcnb + FF, p_h2, nullptr, nullptr);

    // 6) pool over W -> [B, C*F]
    k_pool<<<(BB * CC * FF + 255) / 256, 256>>>();

    // 7) classifier head (fp32 split-K)
    gemm128<false, 0, 0><<<dim3(4, 4, 8), 256>>>(
        p_pool, fc1w, nullptr, p_part, BB, 512, CC * FF, 768);
    k_fcreduce<<<1024, 256>>>(8, fc1b, bn1g, bn1b, bn1m, bn1v, p_z1);
    gemm128<false, 0, 0><<<dim3(4, 4, 4), 256>>>(
        p_z1, fc2w, nullptr, p_part, BB, 512, 512, 128);
    k_fcreduce<<<1024, 256>>>(4, fc2b, bn2g, bn2b, bn2m, bn2v, p_z2);
    k_fc3<<<BB, 128>>>(fc3w, fc3b, out);
}

// round 15
// speedup vs baseline: 1.3278x; 1.3278x over previous
#include <cuda_runtime.h>
#include <cuda_bf16.h>
#include <math.h>
#include <cstdint>

#define BB 512
#define CC 12
#define WW 4
#define FF 512
#define NN 2048      // B*W
#define G3 1536      // 3*F
#define MROWS 24576  // C*N rows

// ---------------- scratch (device globals; no allocation allowed) ----------
__device__ float g_xW [MROWS * G3];    // [C][N][3F] input gate preacts
__device__ float g_hgp[3 * NN * G3];   // split-K partials for recurrent GEMM
__device__ float g_hs [CC * NN * FF];  // [C][N][F]  h after each step
__device__ float g_y1 [BB * CC * FF];
__device__ float g_y2 [BB * CC];
__device__ float g_am [CC * CC];
__device__ float g_cheb[4 * CC * CC];
__device__ float g_h1 [MROWS * FF];    // [C][N][F]
__device__ float g_h2 [MROWS * FF];
__device__ float g_supp[MROWS * FF];
__device__ float g_pool[BB * CC * FF]; // [B, C*F]
__device__ float g_fcpart[8 * 512 * 512];
__device__ float g_z1 [BB * 512];
__device__ float g_z2 [BB * 512];
// bf16 hi/lo planes for tensor-core GEMMs
__device__ __nv_bfloat16 g_axh [MROWS * FF], g_axl [MROWS * FF];   // gathered x
__device__ __nv_bfloat16 g_hbh [CC * NN * FF], g_hbl [CC * NN * FF]; // GRU h
__device__ __nv_bfloat16 g_h1bh[MROWS * FF], g_h1bl[MROWS * FF];   // GCN h1
__device__ __nv_bfloat16 g_wihh[G3 * FF], g_wihl[G3 * FF];
__device__ __nv_bfloat16 g_whhh[G3 * FF], g_whhl[G3 * FF];
__device__ __nv_bfloat16 g_g0h [FF * FF], g_g0l [FF * FF];         // gcnw0^T [N,K]
__device__ __nv_bfloat16 g_g1h [FF * FF], g_g1l [FF * FF];         // gcnw1^T [N,K]

__device__ __forceinline__ void mma16816(float* d, const uint32_t* a, const uint32_t* b) {
    asm volatile(
        "mma.sync.aligned.m16n8k16.row.col.f32.bf16.bf16.f32 "
        "{%0,%1,%2,%3}, {%4,%5,%6,%7}, {%8,%9}, {%0,%1,%2,%3};\n"
        : "+f"(d[0]), "+f"(d[1]), "+f"(d[2]), "+f"(d[3])
        : "r"(a[0]), "r"(a[1]), "r"(a[2]), "r"(a[3]), "r"(b[0]), "r"(b[1]));
}
__device__ __forceinline__ void ldm_x4(uint32_t* r, uint32_t addr) {
    asm volatile("ldmatrix.sync.aligned.m8n8.x4.shared.b16 {%0,%1,%2,%3}, [%4];"
        : "=r"(r[0]), "=r"(r[1]), "=r"(r[2]), "=r"(r[3]) : "r"(addr));
}
__device__ __forceinline__ void split_bf(float v, __nv_bfloat16& h, __nv_bfloat16& l) {
    h = __float2bfloat16(v);
    l = __float2bfloat16(v - __bfloat162float(h));
}

// ================= HMMA bf16 hi/lo split GEMM (fused 3-combo) ===============
// D[M,N] fp32 = (Ah+Al)*(Bh+Bl)^T - Al*Bl^T  (lo*lo dropped)
// 3-stage single-barrier cp.async pipeline; dense 64B rows with chunk-XOR
// swizzle: off(r, k) = r*64 + (((k>>3) ^ (r&3))<<4) + (k&7)*2  — conflict-free.
// kSplit>1: grid.z splits the K chunk range (uneven allowed); partial z -> C + z*M*N.
#define MATB 8192                    // bytes per matrix tile (128 rows x 64B)
#define STAGE4 (4 * MATB)            // Ah|Al|Bh|Bl  = 32768 bytes
#define GEMM_SMEM (3 * STAGE4)       // 98304 bytes (3 stages)

__global__ void __launch_bounds__(256, 2)
gemmMMA(const __nv_bfloat16* __restrict__ Ah, const __nv_bfloat16* __restrict__ Al,
        const __nv_bfloat16* __restrict__ Bh, const __nv_bfloat16* __restrict__ Bl,
        const float* __restrict__ bias, float* __restrict__ C, int M, int N, int K,
        int kSplit)
{
    extern __shared__ __align__(16) char dyn[];
    const uint32_t Su32 = (uint32_t)__cvta_generic_to_shared(dyn);

    const int tid = threadIdx.x, wid = tid >> 5, lane = tid & 31;
    const int wm = wid & 3, wn = wid >> 2;
    const int bm = blockIdx.y * 128, bn = blockIdx.x * 128;
    const int r = lane >> 2, cq = lane & 3;

    const __nv_bfloat16* mat[4] = {
        Ah + (size_t)bm * K, Al + (size_t)bm * K,
        Bh + (size_t)bn * K, Bl + (size_t)bn * K };
    const int KCH = K >> 5;
    const int cps = KCH / kSplit, rem = KCH % kSplit;
    const int z = blockIdx.z;
    const int c0 = z * cps + (z < rem ? z : rem);
    const int c1 = c0 + cps + (z < rem ? 1 : 0);
    C += (size_t)z * M * N;

    float acc[2][8][4];
    #pragma unroll
    for (int mi = 0; mi < 2; mi++)
        #pragma unroll
        for (int ni = 0; ni < 8; ni++)
            #pragma unroll
            for (int q = 0; q < 4; q++) acc[mi][ni][q] = 0.f;

    // prefetch: thread -> (row = tid>>2 [0..63] + i*64, chunk = tid&3)
    const int prow = tid >> 2, pch = tid & 3;
    auto prefetch = [&](int c) {
        const int k0 = c << 5;
        const uint32_t st = (uint32_t)((c % 3) * STAGE4);
        #pragma unroll
        for (int m = 0; m < 4; m++) {
            #pragma unroll
            for (int i = 0; i < 2; i++) {
                const int row = prow + i * 64;
                const uint32_t dst = Su32 + st + (uint32_t)m * MATB +
                                     (uint32_t)row * 64 +
                                     ((uint32_t)(pch ^ (row & 3)) << 4);
                const __nv_bfloat16* src = mat[m] + (size_t)row * K + k0 + pch * 8;
                asm volatile("cp.async.cg.shared.global [%0], [%1], 16;"
                             :: "r"(dst), "l"(src) : "memory");
            }
        }
        asm volatile("cp.async.commit_group;" ::: "memory");
    };

    // per-lane ldmatrix address pieces
    const int a_row = lane & 15;            // row within 16-row block
    const int a_sel = lane >> 4;            // 16B chunk select (0/1)
    const int b_row = ((lane >> 4) << 3) + (lane & 7);
    const int b_sel = (lane >> 3) & 1;
    const int lxor = lane & 3;              // (row & 3) for both A and B phases

    prefetch(c0);
    if (c0 + 1 < c1) prefetch(c0 + 1);
    for (int c = c0; c < c1; c++) {
        if (c + 1 < c1) asm volatile("cp.async.wait_group 1;" ::: "memory");
        else            asm volatile("cp.async.wait_group 0;" ::: "memory");
        __syncthreads();                     // publishes chunk c; retires c-1 readers
        if (c + 2 < c1) prefetch(c + 2);

        const uint32_t S = Su32 + (uint32_t)((c % 3) * STAGE4);
        const uint32_t SAh = S, SAl = S + MATB, SBh = S + 2 * MATB, SBl = S + 3 * MATB;
        #pragma unroll
        for (int ks = 0; ks < 2; ks++) {
            const uint32_t axor = (uint32_t)((ks * 2 + a_sel) ^ lxor) << 4;
            const uint32_t bxor = (uint32_t)((ks * 2 + b_sel) ^ lxor) << 4;
            uint32_t ah[2][4], al[2][4], bf[8][2];
            #pragma unroll
            for (int mi = 0; mi < 2; mi++) {
                const uint32_t ra = (uint32_t)(wm * 32 + mi * 16 + a_row) * 64 + axor;
                ldm_x4(ah[mi], SAh + ra);
            }
            #pragma unroll
            for (int nj = 0; nj < 4; nj++) {
                const uint32_t rb = (uint32_t)(wn * 64 + nj * 16 + b_row) * 64 + bxor;
                uint32_t q[4];
                ldm_x4(q, SBh + rb);
                bf[2 * nj][0] = q[0]; bf[2 * nj][1] = q[1];
                bf[2 * nj + 1][0] = q[2]; bf[2 * nj + 1][1] = q[3];
            }
            #pragma unroll
            for (int mi = 0; mi < 2; mi++)
                #pragma unroll
                for (int ni = 0; ni < 8; ni++)
                    mma16816(acc[mi][ni], ah[mi], bf[ni]);
            #pragma unroll
            for (int mi = 0; mi < 2; mi++) {
                const uint32_t ra = (uint32_t)(wm * 32 + mi * 16 + a_row) * 64 + axor;
                ldm_x4(al[mi], SAl + ra);
            }
            #pragma unroll
            for (int mi = 0; mi < 2; mi++)
                #pragma unroll
                for (int ni = 0; ni < 8; ni++)
                    mma16816(acc[mi][ni], al[mi], bf[ni]);
            #pragma unroll
            for (int nj = 0; nj < 4; nj++) {
                const uint32_t rb = (uint32_t)(wn * 64 + nj * 16 + b_row) * 64 + bxor;
                uint32_t q[4];
                ldm_x4(q, SBl + rb);
                bf[2 * nj][0] = q[0]; bf[2 * nj][1] = q[1];
                bf[2 * nj + 1][0] = q[2]; bf[2 * nj + 1][1] = q[3];
            }
            #pragma unroll
            for (int mi = 0; mi < 2; mi++)
                #pragma unroll
                for (int ni = 0; ni < 8; ni++)
                    mma16816(acc[mi][ni], ah[mi], bf[ni]);
        }
    }

    #pragma unroll
    for (int mi = 0; mi < 2; mi++) {
        const int row0 = bm + wm * 32 + mi * 16 + r;
        #pragma unroll
        for (int ni = 0; ni < 8; ni++) {
            const int col = bn + wn * 64 + ni * 8 + cq * 2;
            float b0 = 0.f, b1 = 0.f;
            if (bias) { b0 = bias[col]; b1 = bias[col + 1]; }
            float2 v0 = make_float2(acc[mi][ni][0] + b0, acc[mi][ni][1] + b1);
            float2 v1 = make_float2(acc[mi][ni][2] + b0, acc[mi][ni][3] + b1);
            *(float2*)&C[(size_t)row0 * N + col] = v0;
            *(float2*)&C[(size_t)(row0 + 8) * N + col] = v1;
        }
    }
}

// ================= fp32 128x128 GEMM (head only) ============================
template<bool TRANSB, int AMAP, int EPI>
__global__ void __launch_bounds__(256, 2)
gemm128(const float* __restrict__ A, const float* __restrict__ B,
        const float* __restrict__ bias, float* __restrict__ C,
        int M, int N, int K, int kChunk)
{
    __shared__ float As[16][132];
    __shared__ float Bs[16][132];
    const int tid = threadIdx.x;
    const int tx = tid & 15, ty = tid >> 4;
    const int bm = blockIdx.y * 128, bn = blockIdx.x * 128;
    int ks = 0, ke = K;
    if (kChunk > 0) {
        ks = blockIdx.z * kChunk; ke = ks + kChunk;
        C += (size_t)blockIdx.z * M * N;
    }
    const int lr = tid >> 2;
    const int lc = (tid & 3) * 4;
    const int bR = tid >> 5;
    const int bC = (tid & 31) * 4;
    size_t aRow0 = (size_t)(bm + lr), aRow1 = (size_t)(bm + lr + 64);

    float4 pa0, pa1, pb0, pb1;
    auto loadg = [&](int k0) {
        pa0 = *(const float4*)&A[aRow0 * K + k0 + lc];
        pa1 = *(const float4*)&A[aRow1 * K + k0 + lc];
        if (TRANSB) {
            pb0 = *(const float4*)&B[(size_t)(bn + lr) * K + k0 + lc];
            pb1 = *(const float4*)&B[(size_t)(bn + lr + 64) * K + k0 + lc];
        } else {
            pb0 = *(const float4*)&B[(size_t)(k0 + bR) * N + bn + bC];
            pb1 = *(const float4*)&B[(size_t)(k0 + bR + 8) * N + bn + bC];
        }
    };
    unsigned long long acc[8][4];
    #pragma unroll
    for (int i = 0; i < 8; i++)
        #pragma unroll
        for (int j = 0; j < 4; j++) acc[i][j] = 0ULL;
    loadg(ks);
    for (int k0 = ks; k0 < ke; k0 += 16) {
        As[lc + 0][lr] = pa0.x; As[lc + 1][lr] = pa0.y;
        As[lc + 2][lr] = pa0.z; As[lc + 3][lr] = pa0.w;
        As[lc + 0][lr + 64] = pa1.x; As[lc + 1][lr + 64] = pa1.y;
        As[lc + 2][lr + 64] = pa1.z; As[lc + 3][lr + 64] = pa1.w;
        if (TRANSB) {
            Bs[lc + 0][lr] = pb0.x; Bs[lc + 1][lr] = pb0.y;
            Bs[lc + 2][lr] = pb0.z; Bs[lc + 3][lr] = pb0.w;
            Bs[lc + 0][lr + 64] = pb1.x; Bs[lc + 1][lr + 64] = pb1.y;
            Bs[lc + 2][lr + 64] = pb1.z; Bs[lc + 3][lr + 64] = pb1.w;
        } else {
            *(float4*)&Bs[bR][bC]     = pb0;
            *(float4*)&Bs[bR + 8][bC] = pb1;
        }
        __syncthreads();
        if (k0 + 16 < ke) loadg(k0 + 16);
        #pragma unroll
        for (int k = 0; k < 16; k++) {
            float4 a0 = *(const float4*)&As[k][ty * 4];
            float4 a1 = *(const float4*)&As[k][64 + ty * 4];
            ulonglong2 b0 = *(const ulonglong2*)&Bs[k][tx * 4];
            ulonglong2 b1 = *(const ulonglong2*)&Bs[k][64 + tx * 4];
            float ar[8] = {a0.x, a0.y, a0.z, a0.w, a1.x, a1.y, a1.z, a1.w};
            unsigned long long bp[4] = {b0.x, b0.y, b1.x, b1.y};
            #pragma unroll
            for (int i = 0; i < 8; i++) {
                unsigned long long ad;
                asm("mov.b64 %0, {%1, %1};" : "=l"(ad) : "f"(ar[i]));
                #pragma unroll
                for (int j = 0; j < 4; j++)
                    asm("fma.rn.f32x2 %0, %1, %2, %0;"
                        : "+l"(acc[i][j]) : "l"(ad), "l"(bp[j]));
            }
        }
        __syncthreads();
    }
    #pragma unroll
    for (int i = 0; i < 8; i++) {
        int gm = bm + ((i < 4) ? (ty * 4 + i) : (60 + ty * 4 + i));
        float v[8];
        #pragma unroll
        for (int j = 0; j < 4; j++)
            asm("mov.b64 {%0, %1}, %2;"
                : "=f"(v[2 * j]), "=f"(v[2 * j + 1]) : "l"(acc[i][j]));
        #pragma unroll
        for (int h = 0; h < 2; h++) {
            int gn = bn + (h ? 64 + tx * 4 : tx * 4);
            float t0 = v[h * 4], t1 = v[h * 4 + 1], t2 = v[h * 4 + 2], t3 = v[h * 4 + 3];
            if (EPI >= 1) {
                t0 += bias[gn + 0]; t1 += bias[gn + 1];
                t2 += bias[gn + 2]; t3 += bias[gn + 3];
            }
            float4 o; o.x = t0; o.y = t1; o.z = t2; o.w = t3;
            *(float4*)&C[(size_t)gm * N + gn] = o;
        }
    }
}

// ================= conversions =============================================
__global__ void k_cvt(const float* __restrict__ src, __nv_bfloat16* __restrict__ hi,
                      __nv_bfloat16* __restrict__ lo, int n) {
    int i = blockIdx.x * blockDim.x + threadIdx.x;
    if (i >= n) return;
    split_bf(src[i], hi[i], lo[i]);
}

// gcn weight [K,N] -> planes [N,K]
__global__ void k_cvtT(const float* __restrict__ W, __nv_bfloat16* __restrict__ hi,
                       __nv_bfloat16* __restrict__ lo) {
    int i = blockIdx.x * blockDim.x + threadIdx.x;
    if (i >= FF * FF) return;
    int n = i >> 9, k = i & 511;
    split_bf(W[k * FF + n], hi[i], lo[i]);
}

// gather x -> A planes [C][N][F]
__global__ void k_cvt_x(const float* __restrict__ x) {
    int idx = blockIdx.x * blockDim.x + threadIdx.x;
    if (idx >= MROWS * FF) return;
    int f = idx & 511;
    int r = idx >> 9;
    int t = r / NN, n = r - t * NN;
    int b = n >> 2, w = n & 3;
    float v = x[(((size_t)b * CC + t) * WW + w) * FF + f];
    split_bf(v, g_axh[idx], g_axl[idx]);
}

// ================= GRU gates (vectorized float4) ============================
__device__ __forceinline__ void gate_store4(size_t o, const float* h) {
    *(float4*)&g_hs[o] = make_float4(h[0], h[1], h[2], h[3]);
    __align__(8) __nv_bfloat16 hh[4], hl[4];
    #pragma unroll
    for (int i = 0; i < 4; i++) split_bf(h[i], hh[i], hl[i]);
    *(uint2*)&g_hbh[o] = *(uint2*)hh;
    *(uint2*)&g_hbl[o] = *(uint2*)hl;
}

__global__ void k_gru_gate0(const float* __restrict__ bhh) {
    int idx = blockIdx.x * blockDim.x + threadIdx.x;
    if (idx >= NN * FF / 4) return;
    int n = idx >> 7, f = (idx & 127) * 4;
    const float* xw = g_xW + (size_t)n * G3;
    float4 xr = *(const float4*)&xw[f];
    float4 xz = *(const float4*)&xw[512 + f];
    float4 xn = *(const float4*)&xw[1024 + f];
    float4 br = *(const float4*)&bhh[f];
    float4 bz = *(const float4*)&bhh[512 + f];
    float4 bn = *(const float4*)&bhh[1024 + f];
    float h[4];
    #pragma unroll
    for (int i = 0; i < 4; i++) {
        float xri = ((const float*)&xr)[i] + ((const float*)&br)[i];
        float xzi = ((const float*)&xz)[i] + ((const float*)&bz)[i];
        float xni = ((const float*)&xn)[i];
        float bni = ((const float*)&bn)[i];
        float r = 1.f / (1.f + expf(-xri));
        float z = 1.f / (1.f + expf(-xzi));
        float nv = tanhf(xni + r * bni);
        h[i] = (1.f - z) * nv;
    }
    gate_store4((size_t)n * FF + f, h);
}

// t>0: sums the three split-K partials of h_prev @ whh^T, adds bhh, gate math.
__global__ void k_gru_gate(int t, const float* __restrict__ bhh) {
    int idx = blockIdx.x * blockDim.x + threadIdx.x;
    if (idx >= NN * FF / 4) return;
    int n = idx >> 7, f = (idx & 127) * 4;
    const size_t base = (size_t)n * G3;
    const float* p0 = g_hgp + base;
    const float* p1 = g_hgp + (size_t)NN * G3 + base;
    const float* p2 = g_hgp + (size_t)2 * NN * G3 + base;
    float hr[4], hz[4], hn[4];
    #pragma unroll
    for (int g = 0; g < 3; g++) {
        float* dst = (g == 0) ? hr : (g == 1) ? hz : hn;
        const int off = g * 512 + f;
        float4 a = *(const float4*)&p0[off];
        float4 b = *(const float4*)&p1[off];
        float4 c = *(const float4*)&p2[off];
        float4 d = *(const float4*)&bhh[off];
        dst[0] = a.x + b.x + c.x + d.x;
        dst[1] = a.y + b.y + c.y + d.y;
        dst[2] = a.z + b.z + c.z + d.z;
        dst[3] = a.w + b.w + c.w + d.w;
    }
    const float* xw = g_xW + ((size_t)t * NN + n) * G3;
    float4 xr = *(const float4*)&xw[f];
    float4 xz = *(const float4*)&xw[512 + f];
    float4 xn = *(const float4*)&xw[1024 + f];
    float4 hp = *(const float4*)&g_hs[((size_t)(t - 1) * NN + n) * FF + f];
    float h[4];
    #pragma unroll
    for (int i = 0; i < 4; i++) {
        float r = 1.f / (1.f + expf(-(((const float*)&xr)[i] + hr[i])));
        float z = 1.f / (1.f + expf(-(((const float*)&xz)[i] + hz[i])));
        float nv = tanhf(((const float*)&xn)[i] + r * hn[i]);
        h[i] = (1.f - z) * nv + z * ((const float*)&hp)[i];
    }
    gate_store4(((size_t)t * NN + n) * FF + f, h);
}

// ================= graph learning ==========================================
// vectorized: one float4 of f per thread
__global__ void k_y1(const float* __restrict__ w, const float* __restrict__ b0) {
    int idx = blockIdx.x * blockDim.x + threadIdx.x;
    if (idx >= BB * CC * FF / 4) return;
    int f = (idx & 127) * 4;
    int r = idx >> 7;           // b*12+c
    int c = r % 12, b = r / 12;
    float w0 = w[0], w1 = w[1], w2 = w[2], w3 = w[3], bb0 = b0[0];
    const float* h0 = &g_hs[((size_t)c * NN + b * 4) * FF + f];
    float4 v0 = *(const float4*)(h0);
    float4 v1 = *(const float4*)(h0 + FF);
    float4 v2 = *(const float4*)(h0 + 2 * FF);
    float4 v3 = *(const float4*)(h0 + 3 * FF);
    float4 o;
    o.x = fmaxf(bb0 + v0.x * w0 + v1.x * w1 + v2.x * w2 + v3.x * w3, 0.f);
    o.y = fmaxf(bb0 + v0.y * w0 + v1.y * w1 + v2.y * w2 + v3.y * w3, 0.f);
    o.z = fmaxf(bb0 + v0.z * w0 + v1.z * w1 + v2.z * w2 + v3.z * w3, 0.f);
    o.w = fmaxf(bb0 + v0.w * w0 + v1.w * w1 + v2.w * w2 + v3.w * w3, 0.f);
    *(float4*)&g_y1[(size_t)r * FF + f] = o;
}

__global__ void k_y2(const float* __restrict__ w, const float* __restrict__ b1) {
    int r = blockIdx.x;
    float s = 0.f;
    for (int f = threadIdx.x; f < 512; f += 128)
        s += g_y1[(size_t)r * 512 + f] * w[f];
    __shared__ float red[4];
    for (int o = 16; o; o >>= 1) s += __shfl_down_sync(0xffffffffu, s, o);
    if ((threadIdx.x & 31) == 0) red[threadIdx.x >> 5] = s;
    __syncthreads();
    if (threadIdx.x == 0)
        g_y2[r] = fmaxf(red[0] + red[1] + red[2] + red[3] + b1[0], 0.f);
}

__global__ void k_y3mean(const float* __restrict__ w2, const float* __restrict__ b2) {
    int k = blockIdx.x;
    float wl[12];
    #pragma unroll
    for (int c = 0; c < 12; c++) wl[c] = w2[k * 12 + c];
    float bk = b2[k];
    float s = 0.f;
    for (int b = threadIdx.x; b < 512; b += 256) {
        float v = bk;
        #pragma unroll
        for (int c = 0; c < 12; c++) v += g_y2[b * 12 + c] * wl[c];
        s += fmaxf(v, 0.f);
    }
    __shared__ float red[8];
    for (int o = 16; o; o >>= 1) s += __shfl_down_sync(0xffffffffu, s, o);
    if ((threadIdx.x & 31) == 0) red[threadIdx.x >> 5] = s;
    __syncthreads();
    if (threadIdx.x == 0) {
        float t = 0.f;
        #pragma unroll
        for (int i = 0; i < 8; i++) t += red[i];
        g_am[k] = t * (1.f / 512.f);
    }
}

__global__ void k_cheb() {
    __shared__ float adj[144], lap[144], L2s[144], deg[12], dh[12];
    int t = threadIdx.x;
    if (t < 144) adj[t] = fmaxf(g_am[t], 0.f);
    __syncthreads();
    if (t < 12) {
        float s = 0.f;
        #pragma unroll
        for (int j = 0; j < 12; j++) s += adj[t * 12 + j];
        deg[t] = s;
        dh[t] = 1.f / (sqrtf(s) + 1e-7f);
    }
    __syncthreads();
    if (t < 144) {
        int i = t / 12, j = t % 12;
        float as = 0.5f * (adj[i * 12 + j] + adj[j * 12 + i]);
        lap[t] = dh[i] * (((i == j) ? deg[i] : 0.f) - as) * dh[j];
    }
    __syncthreads();
    if (t < 144) {
        int i = t / 12, j = t % 12;
        float s = 0.f;
        #pragma unroll
        for (int k = 0; k < 12; k++) s += lap[i * 12 + k] * lap[k * 12 + j];
        L2s[t] = 2.f * s;
    }
    __syncthreads();
    if (t < 144) {
        int i = t / 12, j = t % 12;
        float s = 0.f;
        #pragma unroll
        for (int k = 0; k < 12; k++) s += lap[i * 12 + k] * L2s[k * 12 + j];
        g_cheb[t]       = 0.f;
        g_cheb[144 + t] = lap[t];
        g_cheb[288 + t] = L2s[t];
        g_cheb[432 + t] = 2.f * s - lap[t];
    }
}

// ============ GCN: cheb mix + bias + relu + residual ([C][N][F]) ============
__global__ void k_gcnpost(const float* __restrict__ Hres, const float* __restrict__ gcnb,
                          float* __restrict__ Hout,
                          __nv_bfloat16* __restrict__ Ohi, __nv_bfloat16* __restrict__ Olo) {
    int blk = blockIdx.x;
    int n = blk >> 2;
    int chunk = blk & 3;
    int w = n & 3;
    int f = chunk * 128 + threadIdx.x;
    __shared__ float s[12][129];
    __shared__ float ch[144];
    for (int i = threadIdx.x; i < 144; i += 128) ch[i] = g_cheb[w * 144 + i];
    #pragma unroll
    for (int j = 0; j < 12; j++)
        s[j][threadIdx.x] = g_supp[((size_t)j * NN + n) * 512 + f];
    __syncthreads();
    float bias = gcnb[f];
    #pragma unroll
    for (int i = 0; i < 12; i++) {
        float acc = bias;
        #pragma unroll
        for (int j = 0; j < 12; j++)
            acc = fmaf(ch[i * 12 + j], s[j][threadIdx.x], acc);
        size_t o = ((size_t)i * NN + n) * 512 + f;
        float hv = fmaxf(acc, 0.f) + Hres[o];
        Hout[o] = hv;
        if (Ohi) split_bf(hv, Ohi[o], Olo[o]);
    }
}

// ================= pool over W + flatten (float4) ===========================
__global__ void k_pool() {
    int idx = blockIdx.x * blockDim.x + threadIdx.x;
    if (idx >= BB * CC * FF / 4) return;
    int f = (idx & 127) * 4;
    int r = idx >> 7;           // b*12+c
    int c = r % 12, b = r / 12;
    float4 s = make_float4(0.f, 0.f, 0.f, 0.f);
    #pragma unroll
    for (int w = 0; w < 4; w++) {
        size_t o = ((size_t)c * NN + (b * 4 + w)) * 512 + f;
        float4 a = *(const float4*)&g_hs[o];
        float4 d = *(const float4*)&g_h2[o];
        s.x += a.x + d.x; s.y += a.y + d.y;
        s.z += a.z + d.z; s.w += a.w + d.w;
    }
    *(float4*)&g_pool[(size_t)r * FF + f] = s;
}

// ================= split-K reduce + leaky + BN ==============================
__global__ void k_fcreduce(int S, const float* __restrict__ bias,
                           const float* __restrict__ bng, const float* __restrict__ bnb,
                           const float* __restrict__ bnm, const float* __restrict__ bnv,
                           float* __restrict__ out) {
    int idx = blockIdx.x * blockDim.x + threadIdx.x;
    if (idx >= 512 * 512) return;
    float s = 0.f;
    for (int p = 0; p < S; p++) s += g_fcpart[(size_t)p * 512 * 512 + idx];
    int c = idx & 511;
    s += bias[c];
    s = s > 0.f ? s : 0.01f * s;
    s = (s - bnm[c]) * rsqrtf(bnv[c] + 1e-5f) * bng[c] + bnb[c];
    out[idx] = s;
}

// ================= fc3 (N=4) ================================================
__global__ void k_fc3(const float* __restrict__ w, const float* __restrict__ b,
                      float* __restrict__ out) {
    int bb = blockIdx.x;
    float s0 = 0.f, s1 = 0.f, s2 = 0.f, s3 = 0.f;
    for (int j = threadIdx.x; j < 512; j += 128) {
        float v = g_z2[bb * 512 + j];
        const float* wr = w + j * 4;
        s0 += v * wr[0]; s1 += v * wr[1]; s2 += v * wr[2]; s3 += v * wr[3];
    }
    __shared__ float red[4][4];
    for (int o = 16; o; o >>= 1) {
        s0 += __shfl_down_sync(0xffffffffu, s0, o);
        s1 += __shfl_down_sync(0xffffffffu, s1, o);
        s2 += __shfl_down_sync(0xffffffffu, s2, o);
        s3 += __shfl_down_sync(0xffffffffu, s3, o);
    }
    int wid = threadIdx.x >> 5;
    if ((threadIdx.x & 31) == 0) {
        red[wid][0] = s0; red[wid][1] = s1; red[wid][2] = s2; red[wid][3] = s3;
    }
    __syncthreads();
    if (threadIdx.x < 4) {
        float t = red[0][threadIdx.x] + red[1][threadIdx.x] +
                  red[2][threadIdx.x] + red[3][threadIdx.x];
        out[bb * 4 + threadIdx.x] = t + b[threadIdx.x];
    }
}

// ================= launch ===================================================
extern "C" void kernel_launch(void* const* d_in, const int* in_sizes, int n_in,
                              void* d_out, int out_size) {
    const float* x    = (const float*)d_in[0];
    const float* wih  = (const float*)d_in[1];
    const float* whh  = (const float*)d_in[2];
    const float* bih  = (const float*)d_in[3];
    const float* bhh  = (const float*)d_in[4];
    const float* c0w  = (const float*)d_in[5];
    const float* c0b  = (const float*)d_in[6];
    const float* c1w  = (const float*)d_in[7];
    const float* c1b  = (const float*)d_in[8];
    const float* c2w  = (const float*)d_in[9];
    const float* c2b  = (const float*)d_in[10];
    const float* gcnw = (const float*)d_in[11];
    const float* gcnb = (const float*)d_in[12];
    const float* fc1w = (const float*)d_in[13];
    const float* fc1b = (const float*)d_in[14];
    const float* bn1g = (const float*)d_in[15];
    const float* bn1b = (const float*)d_in[16];
    const float* bn1m = (const float*)d_in[17];
    const float* bn1v = (const float*)d_in[18];
    const float* fc2w = (const float*)d_in[19];
    const float* fc2b = (const float*)d_in[20];
    const float* bn2g = (const float*)d_in[21];
    const float* bn2b = (const float*)d_in[22];
    const float* bn2m = (const float*)d_in[23];
    const float* bn2v = (const float*)d_in[24];
    const float* fc3w = (const float*)d_in[25];
    const float* fc3b = (const float*)d_in[26];
    float* out = (float*)d_out;

    cudaFuncSetAttribute(gemmMMA, cudaFuncAttributeMaxDynamicSharedMemorySize, GEMM_SMEM);

    float *p_xW, *p_hgp, *p_hs, *p_h1, *p_h2, *p_supp, *p_pool, *p_part, *p_z1, *p_z2;
    cudaGetSymbolAddress((void**)&p_xW,  g_xW);
    cudaGetSymbolAddress((void**)&p_hgp, g_hgp);
    cudaGetSymbolAddress((void**)&p_hs,  g_hs);
    cudaGetSymbolAddress((void**)&p_h1,  g_h1);
    cudaGetSymbolAddress((void**)&p_h2,  g_h2);
    cudaGetSymbolAddress((void**)&p_supp, g_supp);
    cudaGetSymbolAddress((void**)&p_pool, g_pool);
    cudaGetSymbolAddress((void**)&p_part, g_fcpart);
    cudaGetSymbolAddress((void**)&p_z1,  g_z1);
    cudaGetSymbolAddress((void**)&p_z2,  g_z2);
    __nv_bfloat16 *p_axh, *p_axl, *p_hbh, *p_hbl, *p_h1bh, *p_h1bl;
    __nv_bfloat16 *p_wihh, *p_wihl, *p_whhh, *p_whhl, *p_g0h, *p_g0l, *p_g1h, *p_g1l;
    cudaGetSymbolAddress((void**)&p_axh,  g_axh);
    cudaGetSymbolAddress((void**)&p_axl,  g_axl);
    cudaGetSymbolAddress((void**)&p_hbh,  g_hbh);
    cudaGetSymbolAddress((void**)&p_hbl,  g_hbl);
    cudaGetSymbolAddress((void**)&p_h1bh, g_h1bh);
    cudaGetSymbolAddress((void**)&p_h1bl, g_h1bl);
    cudaGetSymbolAddress((void**)&p_wihh, g_wihh);
    cudaGetSymbolAddress((void**)&p_wihl, g_wihl);
    cudaGetSymbolAddress((void**)&p_whhh, g_whhh);
    cudaGetSymbolAddress((void**)&p_whhl, g_whhl);
    cudaGetSymbolAddress((void**)&p_g0h,  g_g0h);
    cudaGetSymbolAddress((void**)&p_g0l,  g_g0l);
    cudaGetSymbolAddress((void**)&p_g1h,  g_g1h);
    cudaGetSymbolAddress((void**)&p_g1l,  g_g1l);

    // 0) input-side conversions
    k_cvt_x<<<(MROWS * FF + 255) / 256, 256>>>(x);
    k_cvt<<<(G3 * FF + 255) / 256, 256>>>(wih, p_wihh, p_wihl, G3 * FF);
    k_cvt<<<(G3 * FF + 255) / 256, 256>>>(whh, p_whhh, p_whhl, G3 * FF);

    // 1) input-gate preacts: [24576,1536] = x * wih^T + bih  (HMMA)
    gemmMMA<<<dim3(G3 / 128, MROWS / 128), 256, GEMM_SMEM>>>(
        p_axh, p_axl, p_wihh, p_wihl, bih, p_xW, MROWS, G3, FF, 1);

    // 2) 12 recurrent steps: split-K=3 GEMM (576 blocks)
    k_gru_gate0<<<(NN * FF / 4 + 255) / 256, 256>>>(bhh);
    for (int t = 1; t < CC; t++) {
        gemmMMA<<<dim3(G3 / 128, NN / 128, 3), 256, GEMM_SMEM>>>(
            p_hbh + (size_t)(t - 1) * NN * FF, p_hbl + (size_t)(t - 1) * NN * FF,
            p_whhh, p_whhl, nullptr, p_hgp, NN, G3, FF, 3);
        k_gru_gate<<<(NN * FF / 4 + 255) / 256, 256>>>(t, bhh);
    }

    // 3) graph learning -> chebyshev basis (+ GCN weight conversion)
    k_y1<<<(BB * CC * FF / 4 + 255) / 256, 256>>>(c0w, c0b);
    k_y2<<<BB * CC, 128>>>(c1w, c1b);
    k_y3mean<<<CC * CC, 256>>>(c2w, c2b);
    k_cheb<<<1, 160>>>();
    k_cvtT<<<(FF * FF + 255) / 256, 256>>>(gcnw, p_g0h, p_g0l);
    k_cvtT<<<(FF * FF + 255) / 256, 256>>>(gcnw + FF * FF, p_g1h, p_g1l);

    // 4) GCN layer 0
    gemmMMA<<<dim3(FF / 128, MROWS / 128), 256, GEMM_SMEM>>>(
        p_hbh, p_hbl, p_g0h, p_g0l, nullptr, p_supp, MROWS, FF, FF, 1);
    k_gcnpost<<<NN * 4, 128>>>(p_hs, gcnb, p_h1, p_h1bh, p_h1bl);

    // 5) GCN layer 1
    gemmMMA<<<dim3(FF / 128, MROWS / 128), 256, GEMM_SMEM>>>(
        p_h1bh, p_h1bl, p_g1h, p_g1l, nullptr, p_supp, MROWS, FF, FF, 1);
    k_gcnpost<<<NN * 4, 128>>>(p_h1, gcnb + FF, p_h2, nullptr, nullptr);

    // 6) pool over W -> [B, C*F]
    k_pool<<<(BB * CC * FF / 4 + 255) / 256, 256>>>();

    // 7) classifier head (fp32 split-K)
    gemm128<false, 0, 0><<<dim3(4, 4, 8), 256>>>(
        p_pool, fc1w, nullptr, p_part, BB, 512, CC * FF, 768);
    k_fcreduce<<<1024, 256>>>(8, fc1b, bn1g, bn1b, bn1m, bn1v, p_z1);
    gemm128<false, 0, 0><<<dim3(4, 4, 4), 256>>>(
        p_z1, fc2w, nullptr, p_part, BB, 512, 512, 128);
    k_fcreduce<<<1024, 256>>>(4, fc2b, bn2g, bn2b, bn2m, bn2v, p_z2);
    k_fc3<<<BB, 128>>>(fc3w, fc3b, out);
}

// round 16
// speedup vs baseline: 1.3306x; 1.0021x over previous
#include <cuda_runtime.h>
#include <cuda_bf16.h>
#include <math.h>
#include <cstdint>

#define BB 512
#define CC 12
#define WW 4
#define FF 512
#define NN 2048      // B*W
#define G3 1536      // 3*F
#define MROWS 24576  // C*N rows

// ---------------- scratch (device globals; no allocation allowed) ----------
__device__ float g_xW [MROWS * G3];    // [C][N][3F] input gate preacts
__device__ float g_hgp[3 * NN * G3];   // split-K partials for recurrent GEMM
__device__ float g_hs [CC * NN * FF];  // [C][N][F]  h after each step
__device__ float g_y1 [BB * CC * FF];
__device__ float g_y2 [BB * CC];
__device__ float g_am [CC * CC];
__device__ float g_cheb[4 * CC * CC];
__device__ float g_h1 [MROWS * FF];    // [C][N][F]
__device__ float g_h2 [MROWS * FF];
__device__ float g_supp[MROWS * FF];
__device__ float g_pool[BB * CC * FF]; // [B, C*F]
__device__ float g_fcpart[8 * 512 * 512];
__device__ float g_z1 [BB * 512];
__device__ float g_z2 [BB * 512];
// bf16 hi/lo planes for tensor-core GEMMs
__device__ __nv_bfloat16 g_axh [MROWS * FF], g_axl [MROWS * FF];   // gathered x
__device__ __nv_bfloat16 g_hbh [CC * NN * FF], g_hbl [CC * NN * FF]; // GRU h
__device__ __nv_bfloat16 g_h1bh[MROWS * FF], g_h1bl[MROWS * FF];   // GCN h1
__device__ __nv_bfloat16 g_wihh[G3 * FF], g_wihl[G3 * FF];
__device__ __nv_bfloat16 g_whhh[G3 * FF], g_whhl[G3 * FF];
__device__ __nv_bfloat16 g_g0h [FF * FF], g_g0l [FF * FF];         // gcnw0^T [N,K]
__device__ __nv_bfloat16 g_g1h [FF * FF], g_g1l [FF * FF];         // gcnw1^T [N,K]

__device__ __forceinline__ void mma16816(float* d, const uint32_t* a, const uint32_t* b) {
    asm volatile(
        "mma.sync.aligned.m16n8k16.row.col.f32.bf16.bf16.f32 "
        "{%0,%1,%2,%3}, {%4,%5,%6,%7}, {%8,%9}, {%0,%1,%2,%3};\n"
        : "+f"(d[0]), "+f"(d[1]), "+f"(d[2]), "+f"(d[3])
        : "r"(a[0]), "r"(a[1]), "r"(a[2]), "r"(a[3]), "r"(b[0]), "r"(b[1]));
}
__device__ __forceinline__ void ldm_x4(uint32_t* r, uint32_t addr) {
    asm volatile("ldmatrix.sync.aligned.m8n8.x4.shared.b16 {%0,%1,%2,%3}, [%4];"
        : "=r"(r[0]), "=r"(r[1]), "=r"(r[2]), "=r"(r[3]) : "r"(addr));
}
__device__ __forceinline__ void split_bf(float v, __nv_bfloat16& h, __nv_bfloat16& l) {
    h = __float2bfloat16(v);
    l = __float2bfloat16(v - __bfloat162float(h));
}

// ================= HMMA bf16 hi/lo split GEMM (fused 3-combo) ===============
// D[M,N] fp32 = (Ah+Al)*(Bh+Bl)^T - Al*Bl^T  (lo*lo dropped)
// 3-stage single-barrier cp.async pipeline; dense 64B rows with chunk-XOR
// swizzle: off(r, k) = r*64 + (((k>>3) ^ (r&3))<<4) + (k&7)*2  — conflict-free.
// kSplit>1: grid.z splits K chunks (uneven allowed); partial z -> C + z*pStride.
#define MATB 8192                    // bytes per matrix tile (128 rows x 64B)
#define STAGE4 (4 * MATB)            // Ah|Al|Bh|Bl  = 32768 bytes
#define GEMM_SMEM (3 * STAGE4)       // 98304 bytes (3 stages)

__global__ void __launch_bounds__(256, 2)
gemmMMA(const __nv_bfloat16* __restrict__ Ah, const __nv_bfloat16* __restrict__ Al,
        const __nv_bfloat16* __restrict__ Bh, const __nv_bfloat16* __restrict__ Bl,
        const float* __restrict__ bias, float* __restrict__ C, int M, int N, int K,
        int kSplit, size_t pStride)
{
    extern __shared__ __align__(16) char dyn[];
    const uint32_t Su32 = (uint32_t)__cvta_generic_to_shared(dyn);

    const int tid = threadIdx.x, wid = tid >> 5, lane = tid & 31;
    const int wm = wid & 3, wn = wid >> 2;
    const int bm = blockIdx.y * 128, bn = blockIdx.x * 128;
    const int r = lane >> 2, cq = lane & 3;

    const __nv_bfloat16* mat[4] = {
        Ah + (size_t)bm * K, Al + (size_t)bm * K,
        Bh + (size_t)bn * K, Bl + (size_t)bn * K };
    const int KCH = K >> 5;
    const int cps = KCH / kSplit, rem = KCH % kSplit;
    const int z = blockIdx.z;
    const int c0 = z * cps + (z < rem ? z : rem);
    const int c1 = c0 + cps + (z < rem ? 1 : 0);
    C += (size_t)z * pStride;

    float acc[2][8][4];
    #pragma unroll
    for (int mi = 0; mi < 2; mi++)
        #pragma unroll
        for (int ni = 0; ni < 8; ni++)
            #pragma unroll
            for (int q = 0; q < 4; q++) acc[mi][ni][q] = 0.f;

    // prefetch: thread -> (row = tid>>2 [0..63] + i*64, chunk = tid&3)
    const int prow = tid >> 2, pch = tid & 3;
    auto prefetch = [&](int c) {
        const int k0 = c << 5;
        const uint32_t st = (uint32_t)((c % 3) * STAGE4);
        #pragma unroll
        for (int m = 0; m < 4; m++) {
            #pragma unroll
            for (int i = 0; i < 2; i++) {
                const int row = prow + i * 64;
                const uint32_t dst = Su32 + st + (uint32_t)m * MATB +
                                     (uint32_t)row * 64 +
                                     ((uint32_t)(pch ^ (row & 3)) << 4);
                const __nv_bfloat16* src = mat[m] + (size_t)row * K + k0 + pch * 8;
                asm volatile("cp.async.cg.shared.global [%0], [%1], 16;"
                             :: "r"(dst), "l"(src) : "memory");
            }
        }
        asm volatile("cp.async.commit_group;" ::: "memory");
    };

    // per-lane ldmatrix address pieces
    const int a_row = lane & 15;            // row within 16-row block
    const int a_sel = lane >> 4;            // 16B chunk select (0/1)
    const int b_row = ((lane >> 4) << 3) + (lane & 7);
    const int b_sel = (lane >> 3) & 1;
    const int lxor = lane & 3;              // (row & 3) for both A and B phases

    prefetch(c0);
    if (c0 + 1 < c1) prefetch(c0 + 1);
    for (int c = c0; c < c1; c++) {
        if (c + 1 < c1) asm volatile("cp.async.wait_group 1;" ::: "memory");
        else            asm volatile("cp.async.wait_group 0;" ::: "memory");
        __syncthreads();                     // publishes chunk c; retires c-1 readers
        if (c + 2 < c1) prefetch(c + 2);

        const uint32_t S = Su32 + (uint32_t)((c % 3) * STAGE4);
        const uint32_t SAh = S, SAl = S + MATB, SBh = S + 2 * MATB, SBl = S + 3 * MATB;
        #pragma unroll
        for (int ks = 0; ks < 2; ks++) {
            const uint32_t axor = (uint32_t)((ks * 2 + a_sel) ^ lxor) << 4;
            const uint32_t bxor = (uint32_t)((ks * 2 + b_sel) ^ lxor) << 4;
            uint32_t ah[2][4], al[2][4], bf[8][2];
            #pragma unroll
            for (int mi = 0; mi < 2; mi++) {
                const uint32_t ra = (uint32_t)(wm * 32 + mi * 16 + a_row) * 64 + axor;
                ldm_x4(ah[mi], SAh + ra);
            }
            #pragma unroll
            for (int nj = 0; nj < 4; nj++) {
                const uint32_t rb = (uint32_t)(wn * 64 + nj * 16 + b_row) * 64 + bxor;
                uint32_t q[4];
                ldm_x4(q, SBh + rb);
                bf[2 * nj][0] = q[0]; bf[2 * nj][1] = q[1];
                bf[2 * nj + 1][0] = q[2]; bf[2 * nj + 1][1] = q[3];
            }
            #pragma unroll
            for (int mi = 0; mi < 2; mi++)
                #pragma unroll
                for (int ni = 0; ni < 8; ni++)
                    mma16816(acc[mi][ni], ah[mi], bf[ni]);
            #pragma unroll
            for (int mi = 0; mi < 2; mi++) {
                const uint32_t ra = (uint32_t)(wm * 32 + mi * 16 + a_row) * 64 + axor;
                ldm_x4(al[mi], SAl + ra);
            }
            #pragma unroll
            for (int mi = 0; mi < 2; mi++)
                #pragma unroll
                for (int ni = 0; ni < 8; ni++)
                    mma16816(acc[mi][ni], al[mi], bf[ni]);
            #pragma unroll
            for (int nj = 0; nj < 4; nj++) {
                const uint32_t rb = (uint32_t)(wn * 64 + nj * 16 + b_row) * 64 + bxor;
                uint32_t q[4];
                ldm_x4(q, SBl + rb);
                bf[2 * nj][0] = q[0]; bf[2 * nj][1] = q[1];
                bf[2 * nj + 1][0] = q[2]; bf[2 * nj + 1][1] = q[3];
            }
            #pragma unroll
            for (int mi = 0; mi < 2; mi++)
                #pragma unroll
                for (int ni = 0; ni < 8; ni++)
                    mma16816(acc[mi][ni], ah[mi], bf[ni]);
        }
    }

    #pragma unroll
    for (int mi = 0; mi < 2; mi++) {
        const int row0 = bm + wm * 32 + mi * 16 + r;
        #pragma unroll
        for (int ni = 0; ni < 8; ni++) {
            const int col = bn + wn * 64 + ni * 8 + cq * 2;
            float b0 = 0.f, b1 = 0.f;
            if (bias) { b0 = bias[col]; b1 = bias[col + 1]; }
            float2 v0 = make_float2(acc[mi][ni][0] + b0, acc[mi][ni][1] + b1);
            float2 v1 = make_float2(acc[mi][ni][2] + b0, acc[mi][ni][3] + b1);
            *(float2*)&C[(size_t)row0 * N + col] = v0;
            *(float2*)&C[(size_t)(row0 + 8) * N + col] = v1;
        }
    }
}

// ================= fp32 128x128 GEMM (head only) ============================
template<bool TRANSB, int AMAP, int EPI>
__global__ void __launch_bounds__(256, 2)
gemm128(const float* __restrict__ A, const float* __restrict__ B,
        const float* __restrict__ bias, float* __restrict__ C,
        int M, int N, int K, int kChunk)
{
    __shared__ float As[16][132];
    __shared__ float Bs[16][132];
    const int tid = threadIdx.x;
    const int tx = tid & 15, ty = tid >> 4;
    const int bm = blockIdx.y * 128, bn = blockIdx.x * 128;
    int ks = 0, ke = K;
    if (kChunk > 0) {
        ks = blockIdx.z * kChunk; ke = ks + kChunk;
        C += (size_t)blockIdx.z * M * N;
    }
    const int lr = tid >> 2;
    const int lc = (tid & 3) * 4;
    const int bR = tid >> 5;
    const int bC = (tid & 31) * 4;
    size_t aRow0 = (size_t)(bm + lr), aRow1 = (size_t)(bm + lr + 64);

    float4 pa0, pa1, pb0, pb1;
    auto loadg = [&](int k0) {
        pa0 = *(const float4*)&A[aRow0 * K + k0 + lc];
        pa1 = *(const float4*)&A[aRow1 * K + k0 + lc];
        if (TRANSB) {
            pb0 = *(const float4*)&B[(size_t)(bn + lr) * K + k0 + lc];
            pb1 = *(const float4*)&B[(size_t)(bn + lr + 64) * K + k0 + lc];
        } else {
            pb0 = *(const float4*)&B[(size_t)(k0 + bR) * N + bn + bC];
            pb1 = *(const float4*)&B[(size_t)(k0 + bR + 8) * N + bn + bC];
        }
    };
    unsigned long long acc[8][4];
    #pragma unroll
    for (int i = 0; i < 8; i++)
        #pragma unroll
        for (int j = 0; j < 4; j++) acc[i][j] = 0ULL;
    loadg(ks);
    for (int k0 = ks; k0 < ke; k0 += 16) {
        As[lc + 0][lr] = pa0.x; As[lc + 1][lr] = pa0.y;
        As[lc + 2][lr] = pa0.z; As[lc + 3][lr] = pa0.w;
        As[lc + 0][lr + 64] = pa1.x; As[lc + 1][lr + 64] = pa1.y;
        As[lc + 2][lr + 64] = pa1.z; As[lc + 3][lr + 64] = pa1.w;
        if (TRANSB) {
            Bs[lc + 0][lr] = pb0.x; Bs[lc + 1][lr] = pb0.y;
            Bs[lc + 2][lr] = pb0.z; Bs[lc + 3][lr] = pb0.w;
            Bs[lc + 0][lr + 64] = pb1.x; Bs[lc + 1][lr + 64] = pb1.y;
            Bs[lc + 2][lr + 64] = pb1.z; Bs[lc + 3][lr + 64] = pb1.w;
        } else {
            *(float4*)&Bs[bR][bC]     = pb0;
            *(float4*)&Bs[bR + 8][bC] = pb1;
        }
        __syncthreads();
        if (k0 + 16 < ke) loadg(k0 + 16);
        #pragma unroll
        for (int k = 0; k < 16; k++) {
            float4 a0 = *(const float4*)&As[k][ty * 4];
            float4 a1 = *(const float4*)&As[k][64 + ty * 4];
            ulonglong2 b0 = *(const ulonglong2*)&Bs[k][tx * 4];
            ulonglong2 b1 = *(const ulonglong2*)&Bs[k][64 + tx * 4];
            float ar[8] = {a0.x, a0.y, a0.z, a0.w, a1.x, a1.y, a1.z, a1.w};
            unsigned long long bp[4] = {b0.x, b0.y, b1.x, b1.y};
            #pragma unroll
            for (int i = 0; i < 8; i++) {
                unsigned long long ad;
                asm("mov.b64 %0, {%1, %1};" : "=l"(ad) : "f"(ar[i]));
                #pragma unroll
                for (int j = 0; j < 4; j++)
                    asm("fma.rn.f32x2 %0, %1, %2, %0;"
                        : "+l"(acc[i][j]) : "l"(ad), "l"(bp[j]));
            }
        }
        __syncthreads();
    }
    #pragma unroll
    for (int i = 0; i < 8; i++) {
        int gm = bm + ((i < 4) ? (ty * 4 + i) : (60 + ty * 4 + i));
        float v[8];
        #pragma unroll
        for (int j = 0; j < 4; j++)
            asm("mov.b64 {%0, %1}, %2;"
                : "=f"(v[2 * j]), "=f"(v[2 * j + 1]) : "l"(acc[i][j]));
        #pragma unroll
        for (int h = 0; h < 2; h++) {
            int gn = bn + (h ? 64 + tx * 4 : tx * 4);
            float t0 = v[h * 4], t1 = v[h * 4 + 1], t2 = v[h * 4 + 2], t3 = v[h * 4 + 3];
            if (EPI >= 1) {
                t0 += bias[gn + 0]; t1 += bias[gn + 1];
                t2 += bias[gn + 2]; t3 += bias[gn + 3];
            }
            float4 o; o.x = t0; o.y = t1; o.z = t2; o.w = t3;
            *(float4*)&C[(size_t)gm * N + gn] = o;
        }
    }
}

// ================= conversions =============================================
__global__ void k_cvt(const float* __restrict__ src, __nv_bfloat16* __restrict__ hi,
                      __nv_bfloat16* __restrict__ lo, int n) {
    int i = blockIdx.x * blockDim.x + threadIdx.x;
    if (i >= n) return;
    split_bf(src[i], hi[i], lo[i]);
}

// gcn weight [K,N] -> planes [N,K]
__global__ void k_cvtT(const float* __restrict__ W, __nv_bfloat16* __restrict__ hi,
                       __nv_bfloat16* __restrict__ lo) {
    int i = blockIdx.x * blockDim.x + threadIdx.x;
    if (i >= FF * FF) return;
    int n = i >> 9, k = i & 511;
    split_bf(W[k * FF + n], hi[i], lo[i]);
}

// gather x -> A planes [C][N][F]
__global__ void k_cvt_x(const float* __restrict__ x) {
    int idx = blockIdx.x * blockDim.x + threadIdx.x;
    if (idx >= MROWS * FF) return;
    int f = idx & 511;
    int r = idx >> 9;
    int t = r / NN, n = r - t * NN;
    int b = n >> 2, w = n & 3;
    float v = x[(((size_t)b * CC + t) * WW + w) * FF + f];
    split_bf(v, g_axh[idx], g_axl[idx]);
}

// ================= GRU gates (vectorized float4) ============================
__device__ __forceinline__ void gate_store4(size_t o, const float* h) {
    *(float4*)&g_hs[o] = make_float4(h[0], h[1], h[2], h[3]);
    __align__(8) __nv_bfloat16 hh[4], hl[4];
    #pragma unroll
    for (int i = 0; i < 4; i++) split_bf(h[i], hh[i], hl[i]);
    *(uint2*)&g_hbh[o] = *(uint2*)hh;
    *(uint2*)&g_hbl[o] = *(uint2*)hl;
}

__global__ void k_gru_gate0(const float* __restrict__ bhh) {
    int idx = blockIdx.x * blockDim.x + threadIdx.x;
    if (idx >= NN * FF / 4) return;
    int n = idx >> 7, f = (idx & 127) * 4;
    const float* xw = g_xW + (size_t)n * G3;
    float4 xr = *(const float4*)&xw[f];
    float4 xz = *(const float4*)&xw[512 + f];
    float4 xn = *(const float4*)&xw[1024 + f];
    float4 br = *(const float4*)&bhh[f];
    float4 bz = *(const float4*)&bhh[512 + f];
    float4 bn = *(const float4*)&bhh[1024 + f];
    float h[4];
    #pragma unroll
    for (int i = 0; i < 4; i++) {
        float xri = ((const float*)&xr)[i] + ((const float*)&br)[i];
        float xzi = ((const float*)&xz)[i] + ((const float*)&bz)[i];
        float xni = ((const float*)&xn)[i];
        float bni = ((const float*)&bn)[i];
        float r = 1.f / (1.f + expf(-xri));
        float z = 1.f / (1.f + expf(-xzi));
        float nv = tanhf(xni + r * bni);
        h[i] = (1.f - z) * nv;
    }
    gate_store4((size_t)n * FF + f, h);
}

// t>0: sums the three split-K partials of h_prev @ whh^T, adds bhh, gate math.
// n0: row offset (half-split pipelining).
__global__ void k_gru_gate(int t, const float* __restrict__ bhh, int n0) {
    int idx = blockIdx.x * blockDim.x + threadIdx.x;
    if (idx >= NN * FF / 8) return;
    int n = n0 + (idx >> 7), f = (idx & 127) * 4;
    const size_t base = (size_t)n * G3;
    const float* p0 = g_hgp + base;
    const float* p1 = g_hgp + (size_t)NN * G3 + base;
    const float* p2 = g_hgp + (size_t)2 * NN * G3 + base;
    float hr[4], hz[4], hn[4];
    #pragma unroll
    for (int g = 0; g < 3; g++) {
        float* dst = (g == 0) ? hr : (g == 1) ? hz : hn;
        const int off = g * 512 + f;
        float4 a = *(const float4*)&p0[off];
        float4 b = *(const float4*)&p1[off];
        float4 c = *(const float4*)&p2[off];
        float4 d = *(const float4*)&bhh[off];
        dst[0] = a.x + b.x + c.x + d.x;
        dst[1] = a.y + b.y + c.y + d.y;
        dst[2] = a.z + b.z + c.z + d.z;
        dst[3] = a.w + b.w + c.w + d.w;
    }
    const float* xw = g_xW + ((size_t)t * NN + n) * G3;
    float4 xr = *(const float4*)&xw[f];
    float4 xz = *(const float4*)&xw[512 + f];
    float4 xn = *(const float4*)&xw[1024 + f];
    float4 hp = *(const float4*)&g_hs[((size_t)(t - 1) * NN + n) * FF + f];
    float h[4];
    #pragma unroll
    for (int i = 0; i < 4; i++) {
        float r = 1.f / (1.f + expf(-(((const float*)&xr)[i] + hr[i])));
        float z = 1.f / (1.f + expf(-(((const float*)&xz)[i] + hz[i])));
        float nv = tanhf(((const float*)&xn)[i] + r * hn[i]);
        h[i] = (1.f - z) * nv + z * ((const float*)&hp)[i];
    }
    gate_store4(((size_t)t * NN + n) * FF + f, h);
}

// ================= graph learning ==========================================
__global__ void k_y1(const float* __restrict__ w, const float* __restrict__ b0) {
    int idx = blockIdx.x * blockDim.x + threadIdx.x;
    if (idx >= BB * CC * FF / 4) return;
    int f = (idx & 127) * 4;
    int r = idx >> 7;           // b*12+c
    int c = r % 12, b = r / 12;
    float w0 = w[0], w1 = w[1], w2 = w[2], w3 = w[3], bb0 = b0[0];
    const float* h0 = &g_hs[((size_t)c * NN + b * 4) * FF + f];
    float4 v0 = *(const float4*)(h0);
    float4 v1 = *(const float4*)(h0 + FF);
    float4 v2 = *(const float4*)(h0 + 2 * FF);
    float4 v3 = *(const float4*)(h0 + 3 * FF);
    float4 o;
    o.x = fmaxf(bb0 + v0.x * w0 + v1.x * w1 + v2.x * w2 + v3.x * w3, 0.f);
    o.y = fmaxf(bb0 + v0.y * w0 + v1.y * w1 + v2.y * w2 + v3.y * w3, 0.f);
    o.z = fmaxf(bb0 + v0.z * w0 + v1.z * w1 + v2.z * w2 + v3.z * w3, 0.f);
    o.w = fmaxf(bb0 + v0.w * w0 + v1.w * w1 + v2.w * w2 + v3.w * w3, 0.f);
    *(float4*)&g_y1[(size_t)r * FF + f] = o;
}

__global__ void k_y2(const float* __restrict__ w, const float* __restrict__ b1) {
    int r = blockIdx.x;
    float s = 0.f;
    for (int f = threadIdx.x; f < 512; f += 128)
        s += g_y1[(size_t)r * 512 + f] * w[f];
    __shared__ float red[4];
    for (int o = 16; o; o >>= 1) s += __shfl_down_sync(0xffffffffu, s, o);
    if ((threadIdx.x & 31) == 0) red[threadIdx.x >> 5] = s;
    __syncthreads();
    if (threadIdx.x == 0)
        g_y2[r] = fmaxf(red[0] + red[1] + red[2] + red[3] + b1[0], 0.f);
}

__global__ void k_y3mean(const float* __restrict__ w2, const float* __restrict__ b2) {
    int k = blockIdx.x;
    float wl[12];
    #pragma unroll
    for (int c = 0; c < 12; c++) wl[c] = w2[k * 12 + c];
    float bk = b2[k];
    float s = 0.f;
    for (int b = threadIdx.x; b < 512; b += 256) {
        float v = bk;
        #pragma unroll
        for (int c = 0; c < 12; c++) v += g_y2[b * 12 + c] * wl[c];
        s += fmaxf(v, 0.f);
    }
    __shared__ float red[8];
    for (int o = 16; o; o >>= 1) s += __shfl_down_sync(0xffffffffu, s, o);
    if ((threadIdx.x & 31) == 0) red[threadIdx.x >> 5] = s;
    __syncthreads();
    if (threadIdx.x == 0) {
        float t = 0.f;
        #pragma unroll
        for (int i = 0; i < 8; i++) t += red[i];
        g_am[k] = t * (1.f / 512.f);
    }
}

__global__ void k_cheb() {
    __shared__ float adj[144], lap[144], L2s[144], deg[12], dh[12];
    int t = threadIdx.x;
    if (t < 144) adj[t] = fmaxf(g_am[t], 0.f);
    __syncthreads();
    if (t < 12) {
        float s = 0.f;
        #pragma unroll
        for (int j = 0; j < 12; j++) s += adj[t * 12 + j];
        deg[t] = s;
        dh[t] = 1.f / (sqrtf(s) + 1e-7f);
    }
    __syncthreads();
    if (t < 144) {
        int i = t / 12, j = t % 12;
        float as = 0.5f * (adj[i * 12 + j] + adj[j * 12 + i]);
        lap[t] = dh[i] * (((i == j) ? deg[i] : 0.f) - as) * dh[j];
    }
    __syncthreads();
    if (t < 144) {
        int i = t / 12, j = t % 12;
        float s = 0.f;
        #pragma unroll
        for (int k = 0; k < 12; k++) s += lap[i * 12 + k] * lap[k * 12 + j];
        L2s[t] = 2.f * s;
    }
    __syncthreads();
    if (t < 144) {
        int i = t / 12, j = t % 12;
        float s = 0.f;
        #pragma unroll
        for (int k = 0; k < 12; k++) s += lap[i * 12 + k] * L2s[k * 12 + j];
        g_cheb[t]       = 0.f;
        g_cheb[144 + t] = lap[t];
        g_cheb[288 + t] = L2s[t];
        g_cheb[432 + t] = 2.f * s - lap[t];
    }
}

// ============ GCN: cheb mix + bias + relu + residual ([C][N][F]) ============
__global__ void k_gcnpost(const float* __restrict__ Hres, const float* __restrict__ gcnb,
                          float* __restrict__ Hout,
                          __nv_bfloat16* __restrict__ Ohi, __nv_bfloat16* __restrict__ Olo) {
    int blk = blockIdx.x;
    int n = blk >> 2;
    int chunk = blk & 3;
    int w = n & 3;
    int f = chunk * 128 + threadIdx.x;
    __shared__ float s[12][129];
    __shared__ float ch[144];
    for (int i = threadIdx.x; i < 144; i += 128) ch[i] = g_cheb[w * 144 + i];
    #pragma unroll
    for (int j = 0; j < 12; j++)
        s[j][threadIdx.x] = g_supp[((size_t)j * NN + n) * 512 + f];
    __syncthreads();
    float bias = gcnb[f];
    #pragma unroll
    for (int i = 0; i < 12; i++) {
        float acc = bias;
        #pragma unroll
        for (int j = 0; j < 12; j++)
            acc = fmaf(ch[i * 12 + j], s[j][threadIdx.x], acc);
        size_t o = ((size_t)i * NN + n) * 512 + f;
        float hv = fmaxf(acc, 0.f) + Hres[o];
        Hout[o] = hv;
        if (Ohi) split_bf(hv, Ohi[o], Olo[o]);
    }
}

// ================= pool over W + flatten (float4) ===========================
__global__ void k_pool() {
    int idx = blockIdx.x * blockDim.x + threadIdx.x;
    if (idx >= BB * CC * FF / 4) return;
    int f = (idx & 127) * 4;
    int r = idx >> 7;           // b*12+c
    int c = r % 12, b = r / 12;
    float4 s = make_float4(0.f, 0.f, 0.f, 0.f);
    #pragma unroll
    for (int w = 0; w < 4; w++) {
        size_t o = ((size_t)c * NN + (b * 4 + w)) * 512 + f;
        float4 a = *(const float4*)&g_hs[o];
        float4 d = *(const float4*)&g_h2[o];
        s.x += a.x + d.x; s.y += a.y + d.y;
        s.z += a.z + d.z; s.w += a.w + d.w;
    }
    *(float4*)&g_pool[(size_t)r * FF + f] = s;
}

// ================= split-K reduce + leaky + BN ==============================
__global__ void k_fcreduce(int S, const float* __restrict__ bias,
                           const float* __restrict__ bng, const float* __restrict__ bnb,
                           const float* __restrict__ bnm, const float* __restrict__ bnv,
                           float* __restrict__ out) {
    int idx = blockIdx.x * blockDim.x + threadIdx.x;
    if (idx >= 512 * 512) return;
    float s = 0.f;
    for (int p = 0; p < S; p++) s += g_fcpart[(size_t)p * 512 * 512 + idx];
    int c = idx & 511;
    s += bias[c];
    s = s > 0.f ? s : 0.01f * s;
    s = (s - bnm[c]) * rsqrtf(bnv[c] + 1e-5f) * bng[c] + bnb[c];
    out[idx] = s;
}

// ================= fc3 (N=4) ================================================
__global__ void k_fc3(const float* __restrict__ w, const float* __restrict__ b,
                      float* __restrict__ out) {
    int bb = blockIdx.x;
    float s0 = 0.f, s1 = 0.f, s2 = 0.f, s3 = 0.f;
    for (int j = threadIdx.x; j < 512; j += 128) {
        float v = g_z2[bb * 512 + j];
        const float* wr = w + j * 4;
        s0 += v * wr[0]; s1 += v * wr[1]; s2 += v * wr[2]; s3 += v * wr[3];
    }
    __shared__ float red[4][4];
    for (int o = 16; o; o >>= 1) {
        s0 += __shfl_down_sync(0xffffffffu, s0, o);
        s1 += __shfl_down_sync(0xffffffffu, s1, o);
        s2 += __shfl_down_sync(0xffffffffu, s2, o);
        s3 += __shfl_down_sync(0xffffffffu, s3, o);
    }
    int wid = threadIdx.x >> 5;
    if ((threadIdx.x & 31) == 0) {
        red[wid][0] = s0; red[wid][1] = s1; red[wid][2] = s2; red[wid][3] = s3;
    }
    __syncthreads();
    if (threadIdx.x < 4) {
        float t = red[0][threadIdx.x] + red[1][threadIdx.x] +
                  red[2][threadIdx.x] + red[3][threadIdx.x];
        out[bb * 4 + threadIdx.x] = t + b[threadIdx.x];
    }
}

// ================= launch ===================================================
extern "C" void kernel_launch(void* const* d_in, const int* in_sizes, int n_in,
                              void* d_out, int out_size) {
    const float* x    = (const float*)d_in[0];
    const float* wih  = (const float*)d_in[1];
    const float* whh  = (const float*)d_in[2];
    const float* bih  = (const float*)d_in[3];
    const float* bhh  = (const float*)d_in[4];
    const float* c0w  = (const float*)d_in[5];
    const float* c0b  = (const float*)d_in[6];
    const float* c1w  = (const float*)d_in[7];
    const float* c1b  = (const float*)d_in[8];
    const float* c2w  = (const float*)d_in[9];
    const float* c2b  = (const float*)d_in[10];
    const float* gcnw = (const float*)d_in[11];
    const float* gcnb = (const float*)d_in[12];
    const float* fc1w = (const float*)d_in[13];
    const float* fc1b = (const float*)d_in[14];
    const float* bn1g = (const float*)d_in[15];
    const float* bn1b = (const float*)d_in[16];
    const float* bn1m = (const float*)d_in[17];
    const float* bn1v = (const float*)d_in[18];
    const float* fc2w = (const float*)d_in[19];
    const float* fc2b = (const float*)d_in[20];
    const float* bn2g = (const float*)d_in[21];
    const float* bn2b = (const float*)d_in[22];
    const float* bn2m = (const float*)d_in[23];
    const float* bn2v = (const float*)d_in[24];
    const float* fc3w = (const float*)d_in[25];
    const float* fc3b = (const float*)d_in[26];
    float* out = (float*)d_out;

    cudaFuncSetAttribute(gemmMMA, cudaFuncAttributeMaxDynamicSharedMemorySize, GEMM_SMEM);

    // side stream + event pool (created once; host-side only, no device mem)
    static cudaStream_t s2 = nullptr;
    static cudaEvent_t ev[32];
    if (!s2) {
        cudaStreamCreateWithFlags(&s2, cudaStreamNonBlocking);
        for (int i = 0; i < 32; i++)
            cudaEventCreateWithFlags(&ev[i], cudaEventDisableTiming);
    }
    int ei = 0;

    float *p_xW, *p_hgp, *p_hs, *p_h1, *p_h2, *p_supp, *p_pool, *p_part, *p_z1, *p_z2;
    cudaGetSymbolAddress((void**)&p_xW,  g_xW);
    cudaGetSymbolAddress((void**)&p_hgp, g_hgp);
    cudaGetSymbolAddress((void**)&p_hs,  g_hs);
    cudaGetSymbolAddress((void**)&p_h1,  g_h1);
    cudaGetSymbolAddress((void**)&p_h2,  g_h2);
    cudaGetSymbolAddress((void**)&p_supp, g_supp);
    cudaGetSymbolAddress((void**)&p_pool, g_pool);
    cudaGetSymbolAddress((void**)&p_part, g_fcpart);
    cudaGetSymbolAddress((void**)&p_z1,  g_z1);
    cudaGetSymbolAddress((void**)&p_z2,  g_z2);
    __nv_bfloat16 *p_axh, *p_axl, *p_hbh, *p_hbl, *p_h1bh, *p_h1bl;
    __nv_bfloat16 *p_wihh, *p_wihl, *p_whhh, *p_whhl, *p_g0h, *p_g0l, *p_g1h, *p_g1l;
    cudaGetSymbolAddress((void**)&p_axh,  g_axh);
    cudaGetSymbolAddress((void**)&p_axl,  g_axl);
    cudaGetSymbolAddress((void**)&p_hbh,  g_hbh);
    cudaGetSymbolAddress((void**)&p_hbl,  g_hbl);
    cudaGetSymbolAddress((void**)&p_h1bh, g_h1bh);
    cudaGetSymbolAddress((void**)&p_h1bl, g_h1bl);
    cudaGetSymbolAddress((void**)&p_wihh, g_wihh);
    cudaGetSymbolAddress((void**)&p_wihl, g_wihl);
    cudaGetSymbolAddress((void**)&p_whhh, g_whhh);
    cudaGetSymbolAddress((void**)&p_whhl, g_whhl);
    cudaGetSymbolAddress((void**)&p_g0h,  g_g0h);
    cudaGetSymbolAddress((void**)&p_g0l,  g_g0l);
    cudaGetSymbolAddress((void**)&p_g1h,  g_g1h);
    cudaGetSymbolAddress((void**)&p_g1l,  g_g1l);

    const int halfRows = NN / 2;                       // 1024
    const size_t pStrideFull = (size_t)NN * G3;        // z-partial stride (global)

    // -- fork: side stream does whh cvt + GCN weight cvtTs under xW ----------
    cudaEventRecord(ev[ei], 0); cudaStreamWaitEvent(s2, ev[ei], 0); ei++;
    k_cvt<<<(G3 * FF + 255) / 256, 256, 0, s2>>>(whh, p_whhh, p_whhl, G3 * FF);
    cudaEvent_t eWhh = ev[ei]; cudaEventRecord(eWhh, s2); ei++;
    k_cvtT<<<(FF * FF + 255) / 256, 256, 0, s2>>>(gcnw, p_g0h, p_g0l);
    k_cvtT<<<(FF * FF + 255) / 256, 256, 0, s2>>>(gcnw + FF * FF, p_g1h, p_g1l);
    cudaEvent_t eGw = ev[ei]; cudaEventRecord(eGw, s2); ei++;

    // -- main: x/wih cvt, xW GEMM, gate0 -------------------------------------
    k_cvt_x<<<(MROWS * FF + 255) / 256, 256>>>(x);
    k_cvt<<<(G3 * FF + 255) / 256, 256>>>(wih, p_wihh, p_wihl, G3 * FF);
    gemmMMA<<<dim3(G3 / 128, MROWS / 128), 256, GEMM_SMEM>>>(
        p_axh, p_axl, p_wihh, p_wihl, bih, p_xW, MROWS, G3, FF, 1, 0);
    k_gru_gate0<<<(NN * FF / 4 + 255) / 256, 256>>>(bhh);
    cudaStreamWaitEvent(0, eWhh, 0);

    // -- 12 recurrent steps: half-split GEMM + overlapped gates --------------
    const int gateHalfBlocks = (NN * FF / 8 + 255) / 256;
    for (int t = 1; t < CC; t++) {
        const __nv_bfloat16* ah = p_hbh + (size_t)(t - 1) * NN * FF;
        const __nv_bfloat16* al = p_hbl + (size_t)(t - 1) * NN * FF;
        // half 0 rows [0,1024)
        gemmMMA<<<dim3(G3 / 128, halfRows / 128, 3), 256, GEMM_SMEM>>>(
            ah, al, p_whhh, p_whhl, nullptr, p_hgp, halfRows, G3, FF, 3, pStrideFull);
        cudaEvent_t e0 = ev[ei]; cudaEventRecord(e0, 0); ei++;
        // half 1 rows [1024,2048)
        gemmMMA<<<dim3(G3 / 128, halfRows / 128, 3), 256, GEMM_SMEM>>>(
            ah + (size_t)halfRows * FF, al + (size_t)halfRows * FF,
            p_whhh, p_whhl, nullptr, p_hgp + (size_t)halfRows * G3,
            halfRows, G3, FF, 3, pStrideFull);
        // gate half 0 on side stream, overlapped with GEMM half 1
        cudaStreamWaitEvent(s2, e0, 0);
        k_gru_gate<<<gateHalfBlocks, 256, 0, s2>>>(t, bhh, 0);
        cudaEvent_t e2 = ev[ei]; cudaEventRecord(e2, s2); ei++;
        // gate half 1 on main; then join gate half 0
        k_gru_gate<<<gateHalfBlocks, 256>>>(t, bhh, halfRows);
        cudaStreamWaitEvent(0, e2, 0);
        if (ei > 28) ei = 3;   // reuse step-event slots (prior uses already joined)
    }

    // -- graph-learning chain on side stream, overlapped with GCN0 GEMM ------
    cudaEvent_t eH = ev[29]; cudaEventRecord(eH, 0);
    cudaStreamWaitEvent(s2, eH, 0);
    k_y1<<<(BB * CC * FF / 4 + 255) / 256, 256, 0, s2>>>(c0w, c0b);
    k_y2<<<BB * CC, 128, 0, s2>>>(c1w, c1b);
    k_y3mean<<<CC * CC, 256, 0, s2>>>(c2w, c2b);
    k_cheb<<<1, 160, 0, s2>>>();
    cudaEvent_t eCheb = ev[30]; cudaEventRecord(eCheb, s2);

    cudaStreamWaitEvent(0, eGw, 0);
    gemmMMA<<<dim3(FF / 128, MROWS / 128), 256, GEMM_SMEM>>>(
        p_hbh, p_hbl, p_g0h, p_g0l, nullptr, p_supp, MROWS, FF, FF, 1, 0);
    cudaStreamWaitEvent(0, eCheb, 0);
    k_gcnpost<<<NN * 4, 128>>>(p_hs, gcnb, p_h1, p_h1bh, p_h1bl);

    gemmMMA<<<dim3(FF / 128, MROWS / 128), 256, GEMM_SMEM>>>(
        p_h1bh, p_h1bl, p_g1h, p_g1l, nullptr, p_supp, MROWS, FF, FF, 1, 0);
    k_gcnpost<<<NN * 4, 128>>>(p_h1, gcnb + FF, p_h2, nullptr, nullptr);

    // -- pool + classifier head ----------------------------------------------
    k_pool<<<(BB * CC * FF / 4 + 255) / 256, 256>>>();
    gemm128<false, 0, 0><<<dim3(4, 4, 8), 256>>>(
        p_pool, fc1w, nullptr, p_part, BB, 512, CC * FF, 768);
    k_fcreduce<<<1024, 256>>>(8, fc1b, bn1g, bn1b, bn1m, bn1v, p_z1);
    gemm128<false, 0, 0><<<dim3(4, 4, 4), 256>>>(
        p_z1, fc2w, nullptr, p_part, BB, 512, 512, 128);
    k_fcreduce<<<1024, 256>>>(4, fc2b, bn2g, bn2b, bn2m, bn2v, p_z2);
    k_fc3<<<BB, 128>>>(fc3w, fc3b, out);
}

// round 17
// speedup vs baseline: 1.3720x; 1.0311x over previous
#include <cuda_runtime.h>
#include <cuda_bf16.h>
#include <math.h>
#include <cstdint>

#define BB 512
#define CC 12
#define WW 4
#define FF 512
#define NN 2048      // B*W
#define G3 1536      // 3*F
#define MROWS 24576  // C*N rows

// ---------------- scratch (device globals; no allocation allowed) ----------
__device__ float g_xW [MROWS * G3];    // [C][N][3F] input gate preacts
__device__ float g_hgp[3 * NN * G3];   // split-K partials for recurrent GEMM
__device__ float g_hs [CC * NN * FF];  // [C][N][F]  h after each step
__device__ float g_y1 [BB * CC * FF];
__device__ float g_y2 [BB * CC];
__device__ float g_am [CC * CC];
__device__ float g_cheb[4 * CC * CC];
__device__ float g_h1 [MROWS * FF];    // [C][N][F]
__device__ float g_h2 [MROWS * FF];
__device__ float g_supp[MROWS * FF];
__device__ float g_pool[BB * CC * FF]; // [B, C*F]
__device__ float g_fcpart[8 * 512 * 512];
__device__ float g_z1 [BB * 512];
__device__ float g_z2 [BB * 512];
// bf16 hi/lo planes for tensor-core GEMMs
__device__ __nv_bfloat16 g_axh [MROWS * FF], g_axl [MROWS * FF];   // gathered x
__device__ __nv_bfloat16 g_hbh [CC * NN * FF], g_hbl [CC * NN * FF]; // GRU h
__device__ __nv_bfloat16 g_h1bh[MROWS * FF], g_h1bl[MROWS * FF];   // GCN h1
__device__ __nv_bfloat16 g_wihh[G3 * FF], g_wihl[G3 * FF];
__device__ __nv_bfloat16 g_whhh[G3 * FF], g_whhl[G3 * FF];
__device__ __nv_bfloat16 g_g0h [FF * FF], g_g0l [FF * FF];         // gcnw0^T [N,K]
__device__ __nv_bfloat16 g_g1h [FF * FF], g_g1l [FF * FF];         // gcnw1^T [N,K]

__device__ __forceinline__ void mma16816(float* d, const uint32_t* a, const uint32_t* b) {
    asm volatile(
        "mma.sync.aligned.m16n8k16.row.col.f32.bf16.bf16.f32 "
        "{%0,%1,%2,%3}, {%4,%5,%6,%7}, {%8,%9}, {%0,%1,%2,%3};\n"
        : "+f"(d[0]), "+f"(d[1]), "+f"(d[2]), "+f"(d[3])
        : "r"(a[0]), "r"(a[1]), "r"(a[2]), "r"(a[3]), "r"(b[0]), "r"(b[1]));
}
__device__ __forceinline__ void ldm_x4(uint32_t* r, uint32_t addr) {
    asm volatile("ldmatrix.sync.aligned.m8n8.x4.shared.b16 {%0,%1,%2,%3}, [%4];"
        : "=r"(r[0]), "=r"(r[1]), "=r"(r[2]), "=r"(r[3]) : "r"(addr));
}
__device__ __forceinline__ void split_bf(float v, __nv_bfloat16& h, __nv_bfloat16& l) {
    h = __float2bfloat16(v);
    l = __float2bfloat16(v - __bfloat162float(h));
}
// float4 -> hi/lo uint2 pair
__device__ __forceinline__ void split_bf4(float4 v, uint2& hi, uint2& lo) {
    __align__(8) __nv_bfloat16 hh[4], hl[4];
    split_bf(v.x, hh[0], hl[0]); split_bf(v.y, hh[1], hl[1]);
    split_bf(v.z, hh[2], hl[2]); split_bf(v.w, hh[3], hl[3]);
    hi = *(uint2*)hh; lo = *(uint2*)hl;
}

// ================= HMMA bf16 hi/lo split GEMM (fused 3-combo) ===============
// D[M,N] fp32 = (Ah+Al)*(Bh+Bl)^T - Al*Bl^T  (lo*lo dropped)
// 3-stage single-barrier cp.async pipeline; dense 64B rows with chunk-XOR
// swizzle: off(r, k) = r*64 + (((k>>3) ^ (r&3))<<4) + (k&7)*2  — conflict-free.
// kSplit>1: grid.z splits K chunks (uneven allowed); partial z -> C + z*pStride.
#define MATB 8192                    // bytes per matrix tile (128 rows x 64B)
#define STAGE4 (4 * MATB)            // Ah|Al|Bh|Bl  = 32768 bytes
#define GEMM_SMEM (3 * STAGE4)       // 98304 bytes (3 stages)

__global__ void __launch_bounds__(256, 2)
gemmMMA(const __nv_bfloat16* __restrict__ Ah, const __nv_bfloat16* __restrict__ Al,
        const __nv_bfloat16* __restrict__ Bh, const __nv_bfloat16* __restrict__ Bl,
        const float* __restrict__ bias, float* __restrict__ C, int M, int N, int K,
        int kSplit, size_t pStride)
{
    extern __shared__ __align__(16) char dyn[];
    const uint32_t Su32 = (uint32_t)__cvta_generic_to_shared(dyn);

    const int tid = threadIdx.x, wid = tid >> 5, lane = tid & 31;
    const int wm = wid & 3, wn = wid >> 2;
    const int bm = blockIdx.y * 128, bn = blockIdx.x * 128;
    const int r = lane >> 2, cq = lane & 3;

    const __nv_bfloat16* mat[4] = {
        Ah + (size_t)bm * K, Al + (size_t)bm * K,
        Bh + (size_t)bn * K, Bl + (size_t)bn * K };
    const int KCH = K >> 5;
    const int cps = KCH / kSplit, rem = KCH % kSplit;
    const int z = blockIdx.z;
    const int c0 = z * cps + (z < rem ? z : rem);
    const int c1 = c0 + cps + (z < rem ? 1 : 0);
    C += (size_t)z * pStride;

    float acc[2][8][4];
    #pragma unroll
    for (int mi = 0; mi < 2; mi++)
        #pragma unroll
        for (int ni = 0; ni < 8; ni++)
            #pragma unroll
            for (int q = 0; q < 4; q++) acc[mi][ni][q] = 0.f;

    const int prow = tid >> 2, pch = tid & 3;
    auto prefetch = [&](int c) {
        const int k0 = c << 5;
        const uint32_t st = (uint32_t)((c % 3) * STAGE4);
        #pragma unroll
        for (int m = 0; m < 4; m++) {
            #pragma unroll
            for (int i = 0; i < 2; i++) {
                const int row = prow + i * 64;
                const uint32_t dst = Su32 + st + (uint32_t)m * MATB +
                                     (uint32_t)row * 64 +
                                     ((uint32_t)(pch ^ (row & 3)) << 4);
                const __nv_bfloat16* src = mat[m] + (size_t)row * K + k0 + pch * 8;
                asm volatile("cp.async.cg.shared.global [%0], [%1], 16;"
                             :: "r"(dst), "l"(src) : "memory");
            }
        }
        asm volatile("cp.async.commit_group;" ::: "memory");
    };

    const int a_row = lane & 15;
    const int a_sel = lane >> 4;
    const int b_row = ((lane >> 4) << 3) + (lane & 7);
    const int b_sel = (lane >> 3) & 1;
    const int lxor = lane & 3;

    prefetch(c0);
    if (c0 + 1 < c1) prefetch(c0 + 1);
    for (int c = c0; c < c1; c++) {
        if (c + 1 < c1) asm volatile("cp.async.wait_group 1;" ::: "memory");
        else            asm volatile("cp.async.wait_group 0;" ::: "memory");
        __syncthreads();
        if (c + 2 < c1) prefetch(c + 2);

        const uint32_t S = Su32 + (uint32_t)((c % 3) * STAGE4);
        const uint32_t SAh = S, SAl = S + MATB, SBh = S + 2 * MATB, SBl = S + 3 * MATB;
        #pragma unroll
        for (int ks = 0; ks < 2; ks++) {
            const uint32_t axor = (uint32_t)((ks * 2 + a_sel) ^ lxor) << 4;
            const uint32_t bxor = (uint32_t)((ks * 2 + b_sel) ^ lxor) << 4;
            uint32_t ah[2][4], al[2][4], bf[8][2];
            #pragma unroll
            for (int mi = 0; mi < 2; mi++) {
                const uint32_t ra = (uint32_t)(wm * 32 + mi * 16 + a_row) * 64 + axor;
                ldm_x4(ah[mi], SAh + ra);
            }
            #pragma unroll
            for (int nj = 0; nj < 4; nj++) {
                const uint32_t rb = (uint32_t)(wn * 64 + nj * 16 + b_row) * 64 + bxor;
                uint32_t q[4];
                ldm_x4(q, SBh + rb);
                bf[2 * nj][0] = q[0]; bf[2 * nj][1] = q[1];
                bf[2 * nj + 1][0] = q[2]; bf[2 * nj + 1][1] = q[3];
            }
            #pragma unroll
            for (int mi = 0; mi < 2; mi++)
                #pragma unroll
                for (int ni = 0; ni < 8; ni++)
                    mma16816(acc[mi][ni], ah[mi], bf[ni]);
            #pragma unroll
            for (int mi = 0; mi < 2; mi++) {
                const uint32_t ra = (uint32_t)(wm * 32 + mi * 16 + a_row) * 64 + axor;
                ldm_x4(al[mi], SAl + ra);
            }
            #pragma unroll
            for (int mi = 0; mi < 2; mi++)
                #pragma unroll
                for (int ni = 0; ni < 8; ni++)
                    mma16816(acc[mi][ni], al[mi], bf[ni]);
            #pragma unroll
            for (int nj = 0; nj < 4; nj++) {
                const uint32_t rb = (uint32_t)(wn * 64 + nj * 16 + b_row) * 64 + bxor;
                uint32_t q[4];
                ldm_x4(q, SBl + rb);
                bf[2 * nj][0] = q[0]; bf[2 * nj][1] = q[1];
                bf[2 * nj + 1][0] = q[2]; bf[2 * nj + 1][1] = q[3];
            }
            #pragma unroll
            for (int mi = 0; mi < 2; mi++)
                #pragma unroll
                for (int ni = 0; ni < 8; ni++)
                    mma16816(acc[mi][ni], ah[mi], bf[ni]);
        }
    }

    #pragma unroll
    for (int mi = 0; mi < 2; mi++) {
        const int row0 = bm + wm * 32 + mi * 16 + r;
        #pragma unroll
        for (int ni = 0; ni < 8; ni++) {
            const int col = bn + wn * 64 + ni * 8 + cq * 2;
            float b0 = 0.f, b1 = 0.f;
            if (bias) { b0 = bias[col]; b1 = bias[col + 1]; }
            float2 v0 = make_float2(acc[mi][ni][0] + b0, acc[mi][ni][1] + b1);
            float2 v1 = make_float2(acc[mi][ni][2] + b0, acc[mi][ni][3] + b1);
            *(float2*)&C[(size_t)row0 * N + col] = v0;
            *(float2*)&C[(size_t)(row0 + 8) * N + col] = v1;
        }
    }
}

// ================= fp32 128x128 GEMM (head only) ============================
template<bool TRANSB, int AMAP, int EPI>
__global__ void __launch_bounds__(256, 2)
gemm128(const float* __restrict__ A, const float* __restrict__ B,
        const float* __restrict__ bias, float* __restrict__ C,
        int M, int N, int K, int kChunk)
{
    __shared__ float As[16][132];
    __shared__ float Bs[16][132];
    const int tid = threadIdx.x;
    const int tx = tid & 15, ty = tid >> 4;
    const int bm = blockIdx.y * 128, bn = blockIdx.x * 128;
    int ks = 0, ke = K;
    if (kChunk > 0) {
        ks = blockIdx.z * kChunk; ke = ks + kChunk;
        C += (size_t)blockIdx.z * M * N;
    }
    const int lr = tid >> 2;
    const int lc = (tid & 3) * 4;
    const int bR = tid >> 5;
    const int bC = (tid & 31) * 4;
    size_t aRow0 = (size_t)(bm + lr), aRow1 = (size_t)(bm + lr + 64);

    float4 pa0, pa1, pb0, pb1;
    auto loadg = [&](int k0) {
        pa0 = *(const float4*)&A[aRow0 * K + k0 + lc];
        pa1 = *(const float4*)&A[aRow1 * K + k0 + lc];
        if (TRANSB) {
            pb0 = *(const float4*)&B[(size_t)(bn + lr) * K + k0 + lc];
            pb1 = *(const float4*)&B[(size_t)(bn + lr + 64) * K + k0 + lc];
        } else {
            pb0 = *(const float4*)&B[(size_t)(k0 + bR) * N + bn + bC];
            pb1 = *(const float4*)&B[(size_t)(k0 + bR + 8) * N + bn + bC];
        }
    };
    unsigned long long acc[8][4];
    #pragma unroll
    for (int i = 0; i < 8; i++)
        #pragma unroll
        for (int j = 0; j < 4; j++) acc[i][j] = 0ULL;
    loadg(ks);
    for (int k0 = ks; k0 < ke; k0 += 16) {
        As[lc + 0][lr] = pa0.x; As[lc + 1][lr] = pa0.y;
        As[lc + 2][lr] = pa0.z; As[lc + 3][lr] = pa0.w;
        As[lc + 0][lr + 64] = pa1.x; As[lc + 1][lr + 64] = pa1.y;
        As[lc + 2][lr + 64] = pa1.z; As[lc + 3][lr + 64] = pa1.w;
        if (TRANSB) {
            Bs[lc + 0][lr] = pb0.x; Bs[lc + 1][lr] = pb0.y;
            Bs[lc + 2][lr] = pb0.z; Bs[lc + 3][lr] = pb0.w;
            Bs[lc + 0][lr + 64] = pb1.x; Bs[lc + 1][lr + 64] = pb1.y;
            Bs[lc + 2][lr + 64] = pb1.z; Bs[lc + 3][lr + 64] = pb1.w;
        } else {
            *(float4*)&Bs[bR][bC]     = pb0;
            *(float4*)&Bs[bR + 8][bC] = pb1;
        }
        __syncthreads();
        if (k0 + 16 < ke) loadg(k0 + 16);
        #pragma unroll
        for (int k = 0; k < 16; k++) {
            float4 a0 = *(const float4*)&As[k][ty * 4];
            float4 a1 = *(const float4*)&As[k][64 + ty * 4];
            ulonglong2 b0 = *(const ulonglong2*)&Bs[k][tx * 4];
            ulonglong2 b1 = *(const ulonglong2*)&Bs[k][64 + tx * 4];
            float ar[8] = {a0.x, a0.y, a0.z, a0.w, a1.x, a1.y, a1.z, a1.w};
            unsigned long long bp[4] = {b0.x, b0.y, b1.x, b1.y};
            #pragma unroll
            for (int i = 0; i < 8; i++) {
                unsigned long long ad;
                asm("mov.b64 %0, {%1, %1};" : "=l"(ad) : "f"(ar[i]));
                #pragma unroll
                for (int j = 0; j < 4; j++)
                    asm("fma.rn.f32x2 %0, %1, %2, %0;"
                        : "+l"(acc[i][j]) : "l"(ad), "l"(bp[j]));
            }
        }
        __syncthreads();
    }
    #pragma unroll
    for (int i = 0; i < 8; i++) {
        int gm = bm + ((i < 4) ? (ty * 4 + i) : (60 + ty * 4 + i));
        float v[8];
        #pragma unroll
        for (int j = 0; j < 4; j++)
            asm("mov.b64 {%0, %1}, %2;"
                : "=f"(v[2 * j]), "=f"(v[2 * j + 1]) : "l"(acc[i][j]));
        #pragma unroll
        for (int h = 0; h < 2; h++) {
            int gn = bn + (h ? 64 + tx * 4 : tx * 4);
            float t0 = v[h * 4], t1 = v[h * 4 + 1], t2 = v[h * 4 + 2], t3 = v[h * 4 + 3];
            if (EPI >= 1) {
                t0 += bias[gn + 0]; t1 += bias[gn + 1];
                t2 += bias[gn + 2]; t3 += bias[gn + 3];
            }
            float4 o; o.x = t0; o.y = t1; o.z = t2; o.w = t3;
            *(float4*)&C[(size_t)gm * N + gn] = o;
        }
    }
}

// ================= conversions (vectorized) ================================
__global__ void k_cvt(const float* __restrict__ src, __nv_bfloat16* __restrict__ hi,
                      __nv_bfloat16* __restrict__ lo, int n4) {
    int i = blockIdx.x * blockDim.x + threadIdx.x;
    if (i >= n4) return;
    float4 v = *(const float4*)(src + i * 4);
    uint2 h, l;
    split_bf4(v, h, l);
    *(uint2*)(hi + i * 4) = h;
    *(uint2*)(lo + i * 4) = l;
}

// gcn weight [K,N] -> planes [N,K]  (transposed gather; stays scalar, runs on s2)
__global__ void k_cvtT(const float* __restrict__ W, __nv_bfloat16* __restrict__ hi,
                       __nv_bfloat16* __restrict__ lo) {
    int i = blockIdx.x * blockDim.x + threadIdx.x;
    if (i >= FF * FF) return;
    int n = i >> 9, k = i & 511;
    split_bf(W[k * FF + n], hi[i], lo[i]);
}

// gather x -> A planes [C][N][F]  (float4)
__global__ void k_cvt_x(const float* __restrict__ x) {
    int idx = blockIdx.x * blockDim.x + threadIdx.x;
    if (idx >= MROWS * FF / 4) return;
    int f = (idx & 127) * 4;
    int r = idx >> 7;                 // t*NN + n
    int t = r / NN, n = r - t * NN;
    int b = n >> 2, w = n & 3;
    float4 v = *(const float4*)&x[(((size_t)b * CC + t) * WW + w) * FF + f];
    uint2 h, l;
    split_bf4(v, h, l);
    *(uint2*)(g_axh + (size_t)r * FF + f) = h;
    *(uint2*)(g_axl + (size_t)r * FF + f) = l;
}

// ================= GRU gates (vectorized float4) ============================
__device__ __forceinline__ void gate_store4(size_t o, const float* h) {
    *(float4*)&g_hs[o] = make_float4(h[0], h[1], h[2], h[3]);
    __align__(8) __nv_bfloat16 hh[4], hl[4];
    #pragma unroll
    for (int i = 0; i < 4; i++) split_bf(h[i], hh[i], hl[i]);
    *(uint2*)&g_hbh[o] = *(uint2*)hh;
    *(uint2*)&g_hbl[o] = *(uint2*)hl;
}

__global__ void k_gru_gate0(const float* __restrict__ bhh) {
    int idx = blockIdx.x * blockDim.x + threadIdx.x;
    if (idx >= NN * FF / 4) return;
    int n = idx >> 7, f = (idx & 127) * 4;
    const float* xw = g_xW + (size_t)n * G3;
    float4 xr = *(const float4*)&xw[f];
    float4 xz = *(const float4*)&xw[512 + f];
    float4 xn = *(const float4*)&xw[1024 + f];
    float4 br = *(const float4*)&bhh[f];
    float4 bz = *(const float4*)&bhh[512 + f];
    float4 bn = *(const float4*)&bhh[1024 + f];
    float h[4];
    #pragma unroll
    for (int i = 0; i < 4; i++) {
        float xri = ((const float*)&xr)[i] + ((const float*)&br)[i];
        float xzi = ((const float*)&xz)[i] + ((const float*)&bz)[i];
        float xni = ((const float*)&xn)[i];
        float bni = ((const float*)&bn)[i];
        float r = 1.f / (1.f + expf(-xri));
        float z = 1.f / (1.f + expf(-xzi));
        float nv = tanhf(xni + r * bni);
        h[i] = (1.f - z) * nv;
    }
    gate_store4((size_t)n * FF + f, h);
}

__global__ void k_gru_gate(int t, const float* __restrict__ bhh, int n0) {
    int idx = blockIdx.x * blockDim.x + threadIdx.x;
    if (idx >= NN * FF / 8) return;
    int n = n0 + (idx >> 7), f = (idx & 127) * 4;
    const size_t base = (size_t)n * G3;
    const float* p0 = g_hgp + base;
    const float* p1 = g_hgp + (size_t)NN * G3 + base;
    const float* p2 = g_hgp + (size_t)2 * NN * G3 + base;
    float hr[4], hz[4], hn[4];
    #pragma unroll
    for (int g = 0; g < 3; g++) {
        float* dst = (g == 0) ? hr : (g == 1) ? hz : hn;
        const int off = g * 512 + f;
        float4 a = *(const float4*)&p0[off];
        float4 b = *(const float4*)&p1[off];
        float4 c = *(const float4*)&p2[off];
        float4 d = *(const float4*)&bhh[off];
        dst[0] = a.x + b.x + c.x + d.x;
        dst[1] = a.y + b.y + c.y + d.y;
        dst[2] = a.z + b.z + c.z + d.z;
        dst[3] = a.w + b.w + c.w + d.w;
    }
    const float* xw = g_xW + ((size_t)t * NN + n) * G3;
    float4 xr = *(const float4*)&xw[f];
    float4 xz = *(const float4*)&xw[512 + f];
    float4 xn = *(const float4*)&xw[1024 + f];
    float4 hp = *(const float4*)&g_hs[((size_t)(t - 1) * NN + n) * FF + f];
    float h[4];
    #pragma unroll
    for (int i = 0; i < 4; i++) {
        float r = 1.f / (1.f + expf(-(((const float*)&xr)[i] + hr[i])));
        float z = 1.f / (1.f + expf(-(((const float*)&xz)[i] + hz[i])));
        float nv = tanhf(((const float*)&xn)[i] + r * hn[i]);
        h[i] = (1.f - z) * nv + z * ((const float*)&hp)[i];
    }
    gate_store4(((size_t)t * NN + n) * FF + f, h);
}

// ================= graph learning ==========================================
__global__ void k_y1(const float* __restrict__ w, const float* __restrict__ b0) {
    int idx = blockIdx.x * blockDim.x + threadIdx.x;
    if (idx >= BB * CC * FF / 4) return;
    int f = (idx & 127) * 4;
    int r = idx >> 7;           // b*12+c
    int c = r % 12, b = r / 12;
    float w0 = w[0], w1 = w[1], w2 = w[2], w3 = w[3], bb0 = b0[0];
    const float* h0 = &g_hs[((size_t)c * NN + b * 4) * FF + f];
    float4 v0 = *(const float4*)(h0);
    float4 v1 = *(const float4*)(h0 + FF);
    float4 v2 = *(const float4*)(h0 + 2 * FF);
    float4 v3 = *(const float4*)(h0 + 3 * FF);
    float4 o;
    o.x = fmaxf(bb0 + v0.x * w0 + v1.x * w1 + v2.x * w2 + v3.x * w3, 0.f);
    o.y = fmaxf(bb0 + v0.y * w0 + v1.y * w1 + v2.y * w2 + v3.y * w3, 0.f);
    o.z = fmaxf(bb0 + v0.z * w0 + v1.z * w1 + v2.z * w2 + v3.z * w3, 0.f);
    o.w = fmaxf(bb0 + v0.w * w0 + v1.w * w1 + v2.w * w2 + v3.w * w3, 0.f);
    *(float4*)&g_y1[(size_t)r * FF + f] = o;
}

__global__ void k_y2(const float* __restrict__ w, const float* __restrict__ b1) {
    int r = blockIdx.x;
    float s = 0.f;
    for (int f = threadIdx.x; f < 512; f += 128)
        s += g_y1[(size_t)r * 512 + f] * w[f];
    __shared__ float red[4];
    for (int o = 16; o; o >>= 1) s += __shfl_down_sync(0xffffffffu, s, o);
    if ((threadIdx.x & 31) == 0) red[threadIdx.x >> 5] = s;
    __syncthreads();
    if (threadIdx.x == 0)
        g_y2[r] = fmaxf(red[0] + red[1] + red[2] + red[3] + b1[0], 0.f);
}

__global__ void k_y3mean(const float* __restrict__ w2, const float* __restrict__ b2) {
    int k = blockIdx.x;
    float wl[12];
    #pragma unroll
    for (int c = 0; c < 12; c++) wl[c] = w2[k * 12 + c];
    float bk = b2[k];
    float s = 0.f;
    for (int b = threadIdx.x; b < 512; b += 256) {
        float v = bk;
        #pragma unroll
        for (int c = 0; c < 12; c++) v += g_y2[b * 12 + c] * wl[c];
        s += fmaxf(v, 0.f);
    }
    __shared__ float red[8];
    for (int o = 16; o; o >>= 1) s += __shfl_down_sync(0xffffffffu, s, o);
    if ((threadIdx.x & 31) == 0) red[threadIdx.x >> 5] = s;
    __syncthreads();
    if (threadIdx.x == 0) {
        float t = 0.f;
        #pragma unroll
        for (int i = 0; i < 8; i++) t += red[i];
        g_am[k] = t * (1.f / 512.f);
    }
}

__global__ void k_cheb() {
    __shared__ float adj[144], lap[144], L2s[144], deg[12], dh[12];
    int t = threadIdx.x;
    if (t < 144) adj[t] = fmaxf(g_am[t], 0.f);
    __syncthreads();
    if (t < 12) {
        float s = 0.f;
        #pragma unroll
        for (int j = 0; j < 12; j++) s += adj[t * 12 + j];
        deg[t] = s;
        dh[t] = 1.f / (sqrtf(s) + 1e-7f);
    }
    __syncthreads();
    if (t < 144) {
        int i = t / 12, j = t % 12;
        float as = 0.5f * (adj[i * 12 + j] + adj[j * 12 + i]);
        lap[t] = dh[i] * (((i == j) ? deg[i] : 0.f) - as) * dh[j];
    }
    __syncthreads();
    if (t < 144) {
        int i = t / 12, j = t % 12;
        float s = 0.f;
        #pragma unroll
        for (int k = 0; k < 12; k++) s += lap[i * 12 + k] * lap[k * 12 + j];
        L2s[t] = 2.f * s;
    }
    __syncthreads();
    if (t < 144) {
        int i = t / 12, j = t % 12;
        float s = 0.f;
        #pragma unroll
        for (int k = 0; k < 12; k++) s += lap[i * 12 + k] * L2s[k * 12 + j];
        g_cheb[t]       = 0.f;
        g_cheb[144 + t] = lap[t];
        g_cheb[288 + t] = L2s[t];
        g_cheb[432 + t] = 2.f * s - lap[t];
    }
}

// ============ GCN: cheb mix + bias + relu + residual (float4, [C][N][F]) ====
__global__ void k_gcnpost(const float* __restrict__ Hres, const float* __restrict__ gcnb,
                          float* __restrict__ Hout,
                          __nv_bfloat16* __restrict__ Ohi, __nv_bfloat16* __restrict__ Olo) {
    const int n = blockIdx.x;
    const int w = n & 3;
    const int tid = threadIdx.x;          // 128 threads, f4 = tid*4
    __shared__ float4 s4[12][128];
    __shared__ float ch[144];
    for (int i = tid; i < 144; i += 128) ch[i] = g_cheb[w * 144 + i];
    #pragma unroll
    for (int j = 0; j < 12; j++)
        s4[j][tid] = *(const float4*)&g_supp[((size_t)j * NN + n) * 512 + tid * 4];
    __syncthreads();
    float4 bias = *(const float4*)&gcnb[tid * 4];
    #pragma unroll
    for (int i = 0; i < 12; i++) {
        float4 acc = bias;
        #pragma unroll
        for (int j = 0; j < 12; j++) {
            const float cw = ch[i * 12 + j];
            const float4 sv = s4[j][tid];
            acc.x = fmaf(cw, sv.x, acc.x);
            acc.y = fmaf(cw, sv.y, acc.y);
            acc.z = fmaf(cw, sv.z, acc.z);
            acc.w = fmaf(cw, sv.w, acc.w);
        }
        const size_t o = ((size_t)i * NN + n) * 512 + tid * 4;
        const float4 res = *(const float4*)&Hres[o];
        float4 hv;
        hv.x = fmaxf(acc.x, 0.f) + res.x;
        hv.y = fmaxf(acc.y, 0.f) + res.y;
        hv.z = fmaxf(acc.z, 0.f) + res.z;
        hv.w = fmaxf(acc.w, 0.f) + res.w;
        *(float4*)&Hout[o] = hv;
        if (Ohi) {
            uint2 hh, ll;
            split_bf4(hv, hh, ll);
            *(uint2*)&Ohi[o] = hh;
            *(uint2*)&Olo[o] = ll;
        }
    }
}

// ================= pool over W + flatten (float4) ===========================
__global__ void k_pool() {
    int idx = blockIdx.x * blockDim.x + threadIdx.x;
    if (idx >= BB * CC * FF / 4) return;
    int f = (idx & 127) * 4;
    int r = idx >> 7;           // b*12+c
    int c = r % 12, b = r / 12;
    float4 s = make_float4(0.f, 0.f, 0.f, 0.f);
    #pragma unroll
    for (int w = 0; w < 4; w++) {
        size_t o = ((size_t)c * NN + (b * 4 + w)) * 512 + f;
        float4 a = *(const float4*)&g_hs[o];
        float4 d = *(const float4*)&g_h2[o];
        s.x += a.x + d.x; s.y += a.y + d.y;
        s.z += a.z + d.z; s.w += a.w + d.w;
    }
    *(float4*)&g_pool[(size_t)r * FF + f] = s;
}

// ================= split-K reduce + leaky + BN ==============================
__global__ void k_fcreduce(int S, const float* __restrict__ bias,
                           const float* __restrict__ bng, const float* __restrict__ bnb,
                           const float* __restrict__ bnm, const float* __restrict__ bnv,
                           float* __restrict__ out) {
    int idx = blockIdx.x * blockDim.x + threadIdx.x;
    if (idx >= 512 * 512) return;
    float s = 0.f;
    for (int p = 0; p < S; p++) s += g_fcpart[(size_t)p * 512 * 512 + idx];
    int c = idx & 511;
    s += bias[c];
    s = s > 0.f ? s : 0.01f * s;
    s = (s - bnm[c]) * rsqrtf(bnv[c] + 1e-5f) * bng[c] + bnb[c];
    out[idx] = s;
}

// ================= fc3 (N=4) ================================================
__global__ void k_fc3(const float* __restrict__ w, const float* __restrict__ b,
                      float* __restrict__ out) {
    int bb = blockIdx.x;
    float s0 = 0.f, s1 = 0.f, s2 = 0.f, s3 = 0.f;
    for (int j = threadIdx.x; j < 512; j += 128) {
        float v = g_z2[bb * 512 + j];
        const float* wr = w + j * 4;
        s0 += v * wr[0]; s1 += v * wr[1]; s2 += v * wr[2]; s3 += v * wr[3];
    }
    __shared__ float red[4][4];
    for (int o = 16; o; o >>= 1) {
        s0 += __shfl_down_sync(0xffffffffu, s0, o);
        s1 += __shfl_down_sync(0xffffffffu, s1, o);
        s2 += __shfl_down_sync(0xffffffffu, s2, o);
        s3 += __shfl_down_sync(0xffffffffu, s3, o);
    }
    int wid = threadIdx.x >> 5;
    if ((threadIdx.x & 31) == 0) {
        red[wid][0] = s0; red[wid][1] = s1; red[wid][2] = s2; red[wid][3] = s3;
    }
    __syncthreads();
    if (threadIdx.x < 4) {
        float t = red[0][threadIdx.x] + red[1][threadIdx.x] +
                  red[2][threadIdx.x] + red[3][threadIdx.x];
        out[bb * 4 + threadIdx.x] = t + b[threadIdx.x];
    }
}

// ================= launch ===================================================
extern "C" void kernel_launch(void* const* d_in, const int* in_sizes, int n_in,
                              void* d_out, int out_size) {
    const float* x    = (const float*)d_in[0];
    const float* wih  = (const float*)d_in[1];
    const float* whh  = (const float*)d_in[2];
    const float* bih  = (const float*)d_in[3];
    const float* bhh  = (const float*)d_in[4];
    const float* c0w  = (const float*)d_in[5];
    const float* c0b  = (const float*)d_in[6];
    const float* c1w  = (const float*)d_in[7];
    const float* c1b  = (const float*)d_in[8];
    const float* c2w  = (const float*)d_in[9];
    const float* c2b  = (const float*)d_in[10];
    const float* gcnw = (const float*)d_in[11];
    const float* gcnb = (const float*)d_in[12];
    const float* fc1w = (const float*)d_in[13];
    const float* fc1b = (const float*)d_in[14];
    const float* bn1g = (const float*)d_in[15];
    const float* bn1b = (const float*)d_in[16];
    const float* bn1m = (const float*)d_in[17];
    const float* bn1v = (const float*)d_in[18];
    const float* fc2w = (const float*)d_in[19];
    const float* fc2b = (const float*)d_in[20];
    const float* bn2g = (const float*)d_in[21];
    const float* bn2b = (const float*)d_in[22];
    const float* bn2m = (const float*)d_in[23];
    const float* bn2v = (const float*)d_in[24];
    const float* fc3w = (const float*)d_in[25];
    const float* fc3b = (const float*)d_in[26];
    float* out = (float*)d_out;

    cudaFuncSetAttribute(gemmMMA, cudaFuncAttributeMaxDynamicSharedMemorySize, GEMM_SMEM);

    static cudaStream_t s2 = nullptr;
    static cudaEvent_t ev[32];
    if (!s2) {
        cudaStreamCreateWithFlags(&s2, cudaStreamNonBlocking);
        for (int i = 0; i < 32; i++)
            cudaEventCreateWithFlags(&ev[i], cudaEventDisableTiming);
    }
    int ei = 0;

    float *p_xW, *p_hgp, *p_hs, *p_h1, *p_h2, *p_supp, *p_pool, *p_part, *p_z1, *p_z2;
    cudaGetSymbolAddress((void**)&p_xW,  g_xW);
    cudaGetSymbolAddress((void**)&p_hgp, g_hgp);
    cudaGetSymbolAddress((void**)&p_hs,  g_hs);
    cudaGetSymbolAddress((void**)&p_h1,  g_h1);
    cudaGetSymbolAddress((void**)&p_h2,  g_h2);
    cudaGetSymbolAddress((void**)&p_supp, g_supp);
    cudaGetSymbolAddress((void**)&p_pool, g_pool);
    cudaGetSymbolAddress((void**)&p_part, g_fcpart);
    cudaGetSymbolAddress((void**)&p_z1,  g_z1);
    cudaGetSymbolAddress((void**)&p_z2,  g_z2);
    __nv_bfloat16 *p_axh, *p_axl, *p_hbh, *p_hbl, *p_h1bh, *p_h1bl;
    __nv_bfloat16 *p_wihh, *p_wihl, *p_whhh, *p_whhl, *p_g0h, *p_g0l, *p_g1h, *p_g1l;
    cudaGetSymbolAddress((void**)&p_axh,  g_axh);
    cudaGetSymbolAddress((void**)&p_axl,  g_axl);
    cudaGetSymbolAddress((void**)&p_hbh,  g_hbh);
    cudaGetSymbolAddress((void**)&p_hbl,  g_hbl);
    cudaGetSymbolAddress((void**)&p_h1bh, g_h1bh);
    cudaGetSymbolAddress((void**)&p_h1bl, g_h1bl);
    cudaGetSymbolAddress((void**)&p_wihh, g_wihh);
    cudaGetSymbolAddress((void**)&p_wihl, g_wihl);
    cudaGetSymbolAddress((void**)&p_whhh, g_whhh);
    cudaGetSymbolAddress((void**)&p_whhl, g_whhl);
    cudaGetSymbolAddress((void**)&p_g0h,  g_g0h);
    cudaGetSymbolAddress((void**)&p_g0l,  g_g0l);
    cudaGetSymbolAddress((void**)&p_g1h,  g_g1h);
    cudaGetSymbolAddress((void**)&p_g1l,  g_g1l);

    const int halfRows = NN / 2;
    const size_t pStrideFull = (size_t)NN * G3;

    // -- fork: side stream does whh cvt + GCN weight cvtTs under xW ----------
    cudaEventRecord(ev[ei], 0); cudaStreamWaitEvent(s2, ev[ei], 0); ei++;
    k_cvt<<<(G3 * FF / 4 + 255) / 256, 256, 0, s2>>>(whh, p_whhh, p_whhl, G3 * FF / 4);
    cudaEvent_t eWhh = ev[ei]; cudaEventRecord(eWhh, s2); ei++;
    k_cvtT<<<(FF * FF + 255) / 256, 256, 0, s2>>>(gcnw, p_g0h, p_g0l);
    k_cvtT<<<(FF * FF + 255) / 256, 256, 0, s2>>>(gcnw + FF * FF, p_g1h, p_g1l);
    cudaEvent_t eGw = ev[ei]; cudaEventRecord(eGw, s2); ei++;

    // -- main: x/wih cvt (vectorized), xW GEMM, gate0 ------------------------
    k_cvt_x<<<(MROWS * FF / 4 + 255) / 256, 256>>>(x);
    k_cvt<<<(G3 * FF / 4 + 255) / 256, 256>>>(wih, p_wihh, p_wihl, G3 * FF / 4);
    gemmMMA<<<dim3(G3 / 128, MROWS / 128), 256, GEMM_SMEM>>>(
        p_axh, p_axl, p_wihh, p_wihl, bih, p_xW, MROWS, G3, FF, 1, 0);
    k_gru_gate0<<<(NN * FF / 4 + 255) / 256, 256>>>(bhh);
    cudaStreamWaitEvent(0, eWhh, 0);

    // -- 12 recurrent steps: half-split GEMM + overlapped gates --------------
    const int gateHalfBlocks = (NN * FF / 8 + 255) / 256;
    for (int t = 1; t < CC; t++) {
        const __nv_bfloat16* ah = p_hbh + (size_t)(t - 1) * NN * FF;
        const __nv_bfloat16* al = p_hbl + (size_t)(t - 1) * NN * FF;
        gemmMMA<<<dim3(G3 / 128, halfRows / 128, 3), 256, GEMM_SMEM>>>(
            ah, al, p_whhh, p_whhl, nullptr, p_hgp, halfRows, G3, FF, 3, pStrideFull);
        cudaEvent_t e0 = ev[ei]; cudaEventRecord(e0, 0); ei++;
        gemmMMA<<<dim3(G3 / 128, halfRows / 128, 3), 256, GEMM_SMEM>>>(
            ah + (size_t)halfRows * FF, al + (size_t)halfRows * FF,
            p_whhh, p_whhl, nullptr, p_hgp + (size_t)halfRows * G3,
            halfRows, G3, FF, 3, pStrideFull);
        cudaStreamWaitEvent(s2, e0, 0);
        k_gru_gate<<<gateHalfBlocks, 256, 0, s2>>>(t, bhh, 0);
        cudaEvent_t e2 = ev[ei]; cudaEventRecord(e2, s2); ei++;
        k_gru_gate<<<gateHalfBlocks, 256>>>(t, bhh, halfRows);
        cudaStreamWaitEvent(0, e2, 0);
        if (ei > 28) ei = 3;
    }

    // -- graph-learning chain on side stream, overlapped with GCN0 GEMM ------
    cudaEvent_t eH = ev[29]; cudaEventRecord(eH, 0);
    cudaStreamWaitEvent(s2, eH, 0);
    k_y1<<<(BB * CC * FF / 4 + 255) / 256, 256, 0, s2>>>(c0w, c0b);
    k_y2<<<BB * CC, 128, 0, s2>>>(c1w, c1b);
    k_y3mean<<<CC * CC, 256, 0, s2>>>(c2w, c2b);
    k_cheb<<<1, 160, 0, s2>>>();
    cudaEvent_t eCheb = ev[30]; cudaEventRecord(eCheb, s2);

    cudaStreamWaitEvent(0, eGw, 0);
    gemmMMA<<<dim3(FF / 128, MROWS / 128), 256, GEMM_SMEM>>>(
        p_hbh, p_hbl, p_g0h, p_g0l, nullptr, p_supp, MROWS, FF, FF, 1, 0);
    cudaStreamWaitEvent(0, eCheb, 0);
    k_gcnpost<<<NN, 128>>>(p_hs, gcnb, p_h1, p_h1bh, p_h1bl);

    gemmMMA<<<dim3(FF / 128, MROWS / 128), 256, GEMM_SMEM>>>(
        p_h1bh, p_h1bl, p_g1h, p_g1l, nullptr, p_supp, MROWS, FF, FF, 1, 0);
    k_gcnpost<<<NN, 128>>>(p_h1, gcnb + FF, p_h2, nullptr, nullptr);

    // -- pool + classifier head ----------------------------------------------
    k_pool<<<(BB * CC * FF / 4 + 255) / 256, 256>>>();
    gemm128<false, 0, 0><<<dim3(4, 4, 8), 256>>>(
        p_pool, fc1w, nullptr, p_part, BB, 512, CC * FF, 768);
    k_fcreduce<<<1024, 256>>>(8, fc1b, bn1g, bn1b, bn1m, bn1v, p_z1);
    gemm128<false, 0, 0><<<dim3(4, 4, 4), 256>>>(
        p_z1, fc2w, nullptr, p_part, BB, 512, 512, 128);
    k_fcreduce<<<1024, 256>>>(4, fc2b, bn2g, bn2b, bn2m, bn2v, p_z2);
    k_fc3<<<BB, 128>>>(fc3w, fc3b, out);
}